// round 1
// baseline (speedup 1.0000x reference)
#include <cuda_runtime.h>
#include <cmath>

// Problem constants
#define S_LEN   1024
#define DMODEL  1024
#define H_NUM   16
#define DH      64
#define BATCH   2
#define NCH     16     // chunks along S
#define CHS     64     // chunk length (S_LEN / NCH)

// Scratch (static device globals; no allocation allowed)
__device__ float g_qkv[(size_t)BATCH * S_LEN * 3 * DMODEL];   // 25.2 MB
__device__ float g_attn[(size_t)BATCH * S_LEN * DMODEL];      // 8.4 MB
__device__ float g_den[BATCH * H_NUM * S_LEN];                // 128 KB
__device__ float g_ckv[BATCH * H_NUM * 5 * NCH * DH];         // 640 KB

struct Betas { float b[5]; };

__device__ __forceinline__ float clampx(float x) {
    return fminf(fmaxf(x, -1.0f + 1e-6f), 1.0f - 1e-6f);
}

// Chebyshev T1..T5 (T0=1 implicit; betas for p=0 and p>=6 are exactly zero)
__device__ __forceinline__ void cheb5(float x, float t[5]) {
    float x2 = x + x;
    float t1 = x;
    float t2 = x2 * t1 - 1.0f;
    float t3 = x2 * t2 - t1;
    float t4 = x2 * t3 - t2;
    float t5 = x2 * t4 - t3;
    t[0] = t1; t[1] = t2; t[2] = t3; t[3] = t4; t[4] = t5;
}

// ---------------------------------------------------------------------------
// GEMM: C[M,N] = A[M,K] @ B[N,K]^T   (both row-major, all dims multiple of 128/8)
// 128x128 block tile, BK=8, 256 threads, 8x8 per-thread microtile.
// ---------------------------------------------------------------------------
__global__ __launch_bounds__(256) void gemm_abt(
    const float* __restrict__ A, const float* __restrict__ B,
    float* __restrict__ C, int M, int N, int K)
{
    __shared__ float As[8][128];
    __shared__ float Bs[8][128];

    const int tid  = threadIdx.x;
    const int lrow = tid >> 1;          // 0..127
    const int lk   = (tid & 1) << 2;    // 0 or 4
    const int ty   = tid >> 4;          // 0..15 (m)
    const int tx   = tid & 15;          // 0..15 (n)

    const float* Aptr = A + (size_t)(blockIdx.y * 128 + lrow) * K + lk;
    const float* Bptr = B + (size_t)(blockIdx.x * 128 + lrow) * K + lk;

    float acc[8][8];
#pragma unroll
    for (int i = 0; i < 8; i++)
#pragma unroll
        for (int j = 0; j < 8; j++) acc[i][j] = 0.0f;

    for (int k0 = 0; k0 < K; k0 += 8) {
        float4 av = *(const float4*)(Aptr + k0);
        float4 bv = *(const float4*)(Bptr + k0);
        __syncthreads();
        As[lk + 0][lrow] = av.x; As[lk + 1][lrow] = av.y;
        As[lk + 2][lrow] = av.z; As[lk + 3][lrow] = av.w;
        Bs[lk + 0][lrow] = bv.x; Bs[lk + 1][lrow] = bv.y;
        Bs[lk + 2][lrow] = bv.z; Bs[lk + 3][lrow] = bv.w;
        __syncthreads();
#pragma unroll
        for (int kk = 0; kk < 8; kk++) {
            float a[8], b[8];
            *(float4*)(&a[0]) = *(const float4*)(&As[kk][ty * 8]);
            *(float4*)(&a[4]) = *(const float4*)(&As[kk][ty * 8 + 4]);
            *(float4*)(&b[0]) = *(const float4*)(&Bs[kk][tx * 8]);
            *(float4*)(&b[4]) = *(const float4*)(&Bs[kk][tx * 8 + 4]);
#pragma unroll
            for (int i = 0; i < 8; i++)
#pragma unroll
                for (int j = 0; j < 8; j++)
                    acc[i][j] += a[i] * b[j];
        }
    }

    float* Cp = C + (size_t)(blockIdx.y * 128 + ty * 8) * N + blockIdx.x * 128 + tx * 8;
#pragma unroll
    for (int i = 0; i < 8; i++) {
        *(float4*)(Cp + (size_t)i * N)     = make_float4(acc[i][0], acc[i][1], acc[i][2], acc[i][3]);
        *(float4*)(Cp + (size_t)i * N + 4) = make_float4(acc[i][4], acc[i][5], acc[i][6], acc[i][7]);
    }
}

// ---------------------------------------------------------------------------
// den kernel: one block per (b,h), one thread per s.
//   A_p[s] = sum_d Tq_p(xq[s,d]);  R_p[s] = sum_d Tk_p(xk[s,d])
//   C_p[s] = inclusive scan_s R_p;  den[s] = sum_p beta_p A_p C_p
// ---------------------------------------------------------------------------
__global__ __launch_bounds__(1024) void den_kernel(Betas bt)
{
    const int bh = blockIdx.x;            // 0..31
    const int b = bh >> 4, h = bh & 15;
    const int s = threadIdx.x;

    const float* qrow = g_qkv + ((size_t)(b * S_LEN + s)) * (3 * DMODEL) + h * DH;

    float Aq[5] = {0, 0, 0, 0, 0};
    float Rk[5] = {0, 0, 0, 0, 0};
#pragma unroll 4
    for (int d = 0; d < DH; d++) {
        float tq[5], tk[5];
        cheb5(clampx(qrow[d] * 0.125f), tq);
        cheb5(clampx(qrow[DMODEL + d] * 0.125f), tk);
#pragma unroll
        for (int p = 0; p < 5; p++) { Aq[p] += tq[p]; Rk[p] += tk[p]; }
    }

    // block-wide inclusive scan of Rk over s (5 values)
    const int lane = s & 31, wid = s >> 5;
    __shared__ float wsum[5][32];

    float v[5];
#pragma unroll
    for (int p = 0; p < 5; p++) v[p] = Rk[p];
#pragma unroll
    for (int p = 0; p < 5; p++) {
#pragma unroll
        for (int o = 1; o < 32; o <<= 1) {
            float t = __shfl_up_sync(0xffffffffu, v[p], o);
            if (lane >= o) v[p] += t;
        }
    }
    if (lane == 31) {
#pragma unroll
        for (int p = 0; p < 5; p++) wsum[p][wid] = v[p];
    }
    __syncthreads();
    if (wid == 0) {
#pragma unroll
        for (int p = 0; p < 5; p++) {
            float w = wsum[p][lane];
#pragma unroll
            for (int o = 1; o < 32; o <<= 1) {
                float t = __shfl_up_sync(0xffffffffu, w, o);
                if (lane >= o) w += t;
            }
            wsum[p][lane] = w;   // inclusive warp-sum prefix
        }
    }
    __syncthreads();

    float dsum = 0.0f;
#pragma unroll
    for (int p = 0; p < 5; p++) {
        float C = v[p] + (wid > 0 ? wsum[p][wid - 1] : 0.0f);
        dsum += bt.b[p] * Aq[p] * C;
    }
    g_den[bh * S_LEN + s] = dsum;
}

// ---------------------------------------------------------------------------
// Phase 1: per-chunk sums of Tk_p(xk)*v per (b,h,chunk,d)
// ---------------------------------------------------------------------------
__global__ __launch_bounds__(64) void chunk_kernel()
{
    const int blk = blockIdx.x;                 // b*256 + h*16 + c
    const int c = blk & 15, h = (blk >> 4) & 15, b = blk >> 8;
    const int d = threadIdx.x;

    const float* base = g_qkv + ((size_t)(b * S_LEN + c * CHS)) * (3 * DMODEL)
                        + DMODEL + h * DH + d;   // k stream
    float kv[5] = {0, 0, 0, 0, 0};
    for (int s = 0; s < CHS; s++) {
        float kval = base[(size_t)s * (3 * DMODEL)];
        float vval = base[(size_t)s * (3 * DMODEL) + DMODEL];
        float t[5];
        cheb5(clampx(kval * 0.125f), t);
#pragma unroll
        for (int p = 0; p < 5; p++) kv[p] += t[p] * vval;
    }
    const int bh = b * H_NUM + h;
#pragma unroll
    for (int p = 0; p < 5; p++)
        g_ckv[(((size_t)bh * 5 + p) * NCH + c) * DH + d] = kv[p];
}

// ---------------------------------------------------------------------------
// Phase 2: exclusive prefix over chunks, in place. One thread per (b,h,p,d).
// ---------------------------------------------------------------------------
__global__ void prefix_kernel()
{
    const int t = blockIdx.x * blockDim.x + threadIdx.x;
    if (t >= BATCH * H_NUM * 5 * DH) return;
    const int d = t & 63;
    const int bhp = t >> 6;                     // = bh*5 + p
    const size_t base = (size_t)bhp * NCH * DH + d;
    float run = 0.0f;
    for (int c = 0; c < NCH; c++) {
        size_t idx = base + (size_t)c * DH;
        float tmp = g_ckv[idx];
        g_ckv[idx] = run;
        run += tmp;
    }
}

// ---------------------------------------------------------------------------
// Phase 3: rescan chunk with exclusive offset; fuse numerator + normalize.
// ---------------------------------------------------------------------------
__global__ __launch_bounds__(64) void final_kernel(Betas bt)
{
    const int blk = blockIdx.x;
    const int c = blk & 15, h = (blk >> 4) & 15, b = blk >> 8;
    const int d = threadIdx.x;
    const int bh = b * H_NUM + h;

    float kv[5];
#pragma unroll
    for (int p = 0; p < 5; p++)
        kv[p] = g_ckv[(((size_t)bh * 5 + p) * NCH + c) * DH + d];

    const float* base = g_qkv + ((size_t)(b * S_LEN + c * CHS)) * (3 * DMODEL) + h * DH + d;
    const float* denb = g_den + bh * S_LEN + c * CHS;
    float* ob = g_attn + ((size_t)(b * S_LEN + c * CHS)) * DMODEL + h * DH + d;

    for (int s = 0; s < CHS; s++) {
        const float* r = base + (size_t)s * (3 * DMODEL);
        float qv = r[0];
        float kval = r[DMODEL];
        float vval = r[2 * DMODEL];

        float tk[5];
        cheb5(clampx(kval * 0.125f), tk);
#pragma unroll
        for (int p = 0; p < 5; p++) kv[p] += tk[p] * vval;

        float tq[5];
        cheb5(clampx(qv * 0.125f), tq);
        float num = 0.0f;
#pragma unroll
        for (int p = 0; p < 5; p++) num += bt.b[p] * tq[p] * kv[p];

        ob[(size_t)s * DMODEL] = num / (denb[s] + 1e-7f);
    }
}

// ---------------------------------------------------------------------------
extern "C" void kernel_launch(void* const* d_in, const int* in_sizes, int n_in,
                              void* d_out, int out_size)
{
    const float* x     = (const float*)d_in[0];   // (2,1024,1024)
    const float* W_in  = (const float*)d_in[1];   // (3072,1024)
    const float* W_out = (const float*)d_in[2];   // (1024,1024)
    float* out = (float*)d_out;                   // (2,1024,1024)

    float *qkv, *attn;
    cudaGetSymbolAddress((void**)&qkv, g_qkv);
    cudaGetSymbolAddress((void**)&attn, g_attn);

    // beta[p] = tail[p] / sum(tail[1..5]),  tail[j] = sum_{i>=j} (i+1)^{-1.5}
    double alpha[6], tail[7];
    tail[6] = 0.0;
    for (int j = 5; j >= 0; j--) {
        alpha[j] = pow((double)(j + 1), -1.5);
        tail[j] = tail[j + 1] + alpha[j];
    }
    double bsum = tail[1] + tail[2] + tail[3] + tail[4] + tail[5];
    Betas bt;
    for (int p = 0; p < 5; p++) bt.b[p] = (float)(tail[p + 1] / bsum);

    const int M = BATCH * S_LEN;   // 2048

    gemm_abt<<<dim3(3 * DMODEL / 128, M / 128), 256>>>(x, W_in, qkv, M, 3 * DMODEL, DMODEL);
    den_kernel<<<BATCH * H_NUM, 1024>>>(bt);
    chunk_kernel<<<BATCH * H_NUM * NCH, 64>>>();
    prefix_kernel<<<(BATCH * H_NUM * 5 * DH + 255) / 256, 256>>>();
    final_kernel<<<BATCH * H_NUM * NCH, 64>>>(bt);
    gemm_abt<<<dim3(DMODEL / 128, M / 128), 256>>>(attn, W_out, out, M, DMODEL, DMODEL);
}

// round 2
// speedup vs baseline: 1.1715x; 1.1715x over previous
#include <cuda_runtime.h>
#include <cmath>

// Problem constants
#define S_LEN   1024
#define DMODEL  1024
#define H_NUM   16
#define DH      64
#define BATCH   2
#define NCH     16     // chunks along S
#define CHS     64     // chunk length (S_LEN / NCH)

// Scratch (static device globals; no allocation allowed)
__device__ float g_qkv[(size_t)BATCH * S_LEN * 3 * DMODEL];   // 25.2 MB
__device__ float g_attn[(size_t)BATCH * S_LEN * DMODEL];      // 8.4 MB
__device__ float g_den[BATCH * H_NUM * S_LEN];                // 128 KB
__device__ float g_ckv[BATCH * H_NUM * 5 * NCH * DH];         // 640 KB

struct Betas { float b[5]; };

__device__ __forceinline__ float clampx(float x) {
    return fminf(fmaxf(x, -1.0f + 1e-6f), 1.0f - 1e-6f);
}

// Chebyshev T1..T5 (T0=1 implicit; betas for p=0 and p>=6 are exactly zero)
__device__ __forceinline__ void cheb5(float x, float t[5]) {
    float x2 = x + x;
    float t1 = x;
    float t2 = x2 * t1 - 1.0f;
    float t3 = x2 * t2 - t1;
    float t4 = x2 * t3 - t2;
    float t5 = x2 * t4 - t3;
    t[0] = t1; t[1] = t2; t[2] = t3; t[3] = t4; t[4] = t5;
}

__device__ __forceinline__ unsigned f2tf32(float x) {
    unsigned u;
    asm("cvt.rna.tf32.f32 %0, %1;" : "=r"(u) : "f"(x));
    return u;
}

__device__ __forceinline__ void mma_tf32(float c[4],
                                         unsigned a0, unsigned a1, unsigned a2, unsigned a3,
                                         unsigned b0, unsigned b1) {
    asm volatile(
        "mma.sync.aligned.m16n8k8.row.col.f32.tf32.tf32.f32 "
        "{%0,%1,%2,%3}, {%4,%5,%6,%7}, {%8,%9}, {%0,%1,%2,%3};"
        : "+f"(c[0]), "+f"(c[1]), "+f"(c[2]), "+f"(c[3])
        : "r"(a0), "r"(a1), "r"(a2), "r"(a3), "r"(b0), "r"(b1));
}

// ---------------------------------------------------------------------------
// TF32x3 tensor-core GEMM: C[M,N] = A[M,K] @ B[N,K]^T   (row-major)
// BM=BN=128, BK=16, 256 threads (8 warps, 2x4), warp tile 64x32.
// hi/lo tf32 split precomputed into smem; 3 mma passes (hh, hl, lh).
// ---------------------------------------------------------------------------
#define SPITCH 136   // 16*136*4B per array; (136*k + m) % 32 = (8k+m)%32 -> conflict-free frags

__global__ __launch_bounds__(256) void gemm_tf32x3(
    const float* __restrict__ A, const float* __restrict__ B,
    float* __restrict__ C, int M, int N, int K)
{
    __shared__ float Ah[16 * SPITCH], Al[16 * SPITCH];
    __shared__ float Bh[16 * SPITCH], Bl[16 * SPITCH];

    const int tid  = threadIdx.x;
    const int wid  = tid >> 5;
    const int lane = tid & 31;
    const int wm = (wid >> 2) * 64;   // warp m offset in tile
    const int wn = (wid & 3) * 32;    // warp n offset in tile
    const int g  = lane >> 2;         // 0..7
    const int th = lane & 3;          // 0..3

    const int bm = blockIdx.y * 128;
    const int bn = blockIdx.x * 128;

    // gmem load mapping: float4 idx = tid (rows 0..63) and tid+256 (rows 64..127)
    const int r0 = tid >> 2,  c0 = (tid & 3) * 4;        // row, k-col of f4 #0
    const int r1 = r0 + 64;                              // f4 #1 same col group

    const float* Ag0 = A + (size_t)(bm + r0) * K + c0;
    const float* Ag1 = A + (size_t)(bm + r1) * K + c0;
    const float* Bg0 = B + (size_t)(bn + r0) * K + c0;
    const float* Bg1 = B + (size_t)(bn + r1) * K + c0;

    float acc[4][4][4];
#pragma unroll
    for (int i = 0; i < 4; i++)
#pragma unroll
        for (int j = 0; j < 4; j++)
#pragma unroll
            for (int r = 0; r < 4; r++) acc[i][j][r] = 0.0f;

    float4 a0v = *(const float4*)Ag0;
    float4 a1v = *(const float4*)Ag1;
    float4 b0v = *(const float4*)Bg0;
    float4 b1v = *(const float4*)Bg1;

    for (int k0 = 0; k0 < K; k0 += 16) {
        __syncthreads();
        // split + store to smem
        {
            const float av0[4] = {a0v.x, a0v.y, a0v.z, a0v.w};
            const float av1[4] = {a1v.x, a1v.y, a1v.z, a1v.w};
            const float bv0[4] = {b0v.x, b0v.y, b0v.z, b0v.w};
            const float bv1[4] = {b1v.x, b1v.y, b1v.z, b1v.w};
#pragma unroll
            for (int j = 0; j < 4; j++) {
                int k = c0 + j;
                unsigned h;
                float hf;
                h = f2tf32(av0[j]); hf = __uint_as_float(h);
                Ah[k * SPITCH + r0] = hf;
                Al[k * SPITCH + r0] = __uint_as_float(f2tf32(av0[j] - hf));
                h = f2tf32(av1[j]); hf = __uint_as_float(h);
                Ah[k * SPITCH + r1] = hf;
                Al[k * SPITCH + r1] = __uint_as_float(f2tf32(av1[j] - hf));
                h = f2tf32(bv0[j]); hf = __uint_as_float(h);
                Bh[k * SPITCH + r0] = hf;
                Bl[k * SPITCH + r0] = __uint_as_float(f2tf32(bv0[j] - hf));
                h = f2tf32(bv1[j]); hf = __uint_as_float(h);
                Bh[k * SPITCH + r1] = hf;
                Bl[k * SPITCH + r1] = __uint_as_float(f2tf32(bv1[j] - hf));
            }
        }
        __syncthreads();

        // prefetch next tile
        if (k0 + 16 < K) {
            a0v = *(const float4*)(Ag0 + k0 + 16);
            a1v = *(const float4*)(Ag1 + k0 + 16);
            b0v = *(const float4*)(Bg0 + k0 + 16);
            b1v = *(const float4*)(Bg1 + k0 + 16);
        }

#pragma unroll
        for (int kk = 0; kk < 16; kk += 8) {
            unsigned ah[4][4], al[4][4];
#pragma unroll
            for (int mf = 0; mf < 4; mf++) {
                int r = wm + mf * 16;
                ah[mf][0] = __float_as_uint(Ah[(kk + th) * SPITCH + r + g]);
                ah[mf][1] = __float_as_uint(Ah[(kk + th) * SPITCH + r + g + 8]);
                ah[mf][2] = __float_as_uint(Ah[(kk + th + 4) * SPITCH + r + g]);
                ah[mf][3] = __float_as_uint(Ah[(kk + th + 4) * SPITCH + r + g + 8]);
                al[mf][0] = __float_as_uint(Al[(kk + th) * SPITCH + r + g]);
                al[mf][1] = __float_as_uint(Al[(kk + th) * SPITCH + r + g + 8]);
                al[mf][2] = __float_as_uint(Al[(kk + th + 4) * SPITCH + r + g]);
                al[mf][3] = __float_as_uint(Al[(kk + th + 4) * SPITCH + r + g + 8]);
            }
            unsigned bh[4][2], bl[4][2];
#pragma unroll
            for (int nf = 0; nf < 4; nf++) {
                int cn = wn + nf * 8;
                bh[nf][0] = __float_as_uint(Bh[(kk + th) * SPITCH + cn + g]);
                bh[nf][1] = __float_as_uint(Bh[(kk + th + 4) * SPITCH + cn + g]);
                bl[nf][0] = __float_as_uint(Bl[(kk + th) * SPITCH + cn + g]);
                bl[nf][1] = __float_as_uint(Bl[(kk + th + 4) * SPITCH + cn + g]);
            }
#pragma unroll
            for (int mf = 0; mf < 4; mf++)
#pragma unroll
                for (int nf = 0; nf < 4; nf++) {
                    mma_tf32(acc[mf][nf], ah[mf][0], ah[mf][1], ah[mf][2], ah[mf][3],
                             bh[nf][0], bh[nf][1]);
                    mma_tf32(acc[mf][nf], ah[mf][0], ah[mf][1], ah[mf][2], ah[mf][3],
                             bl[nf][0], bl[nf][1]);
                    mma_tf32(acc[mf][nf], al[mf][0], al[mf][1], al[mf][2], al[mf][3],
                             bh[nf][0], bh[nf][1]);
                }
        }
    }

    // epilogue
#pragma unroll
    for (int mf = 0; mf < 4; mf++) {
#pragma unroll
        for (int nf = 0; nf < 4; nf++) {
            int row = bm + wm + mf * 16 + g;
            int col = bn + wn + nf * 8 + 2 * th;
            *(float2*)(C + (size_t)row * N + col) =
                make_float2(acc[mf][nf][0], acc[mf][nf][1]);
            *(float2*)(C + (size_t)(row + 8) * N + col) =
                make_float2(acc[mf][nf][2], acc[mf][nf][3]);
        }
    }
}

// ---------------------------------------------------------------------------
// den kernel: one block per (b,h), one thread per s.
// ---------------------------------------------------------------------------
__global__ __launch_bounds__(1024) void den_kernel(Betas bt)
{
    const int bh = blockIdx.x;            // 0..31
    const int b = bh >> 4, h = bh & 15;
    const int s = threadIdx.x;

    const float* qrow = g_qkv + ((size_t)(b * S_LEN + s)) * (3 * DMODEL) + h * DH;

    float Aq[5] = {0, 0, 0, 0, 0};
    float Rk[5] = {0, 0, 0, 0, 0};
#pragma unroll 4
    for (int d = 0; d < DH; d++) {
        float tq[5], tk[5];
        cheb5(clampx(qrow[d] * 0.125f), tq);
        cheb5(clampx(qrow[DMODEL + d] * 0.125f), tk);
#pragma unroll
        for (int p = 0; p < 5; p++) { Aq[p] += tq[p]; Rk[p] += tk[p]; }
    }

    const int lane = s & 31, wid = s >> 5;
    __shared__ float wsum[5][32];

    float v[5];
#pragma unroll
    for (int p = 0; p < 5; p++) v[p] = Rk[p];
#pragma unroll
    for (int p = 0; p < 5; p++) {
#pragma unroll
        for (int o = 1; o < 32; o <<= 1) {
            float t = __shfl_up_sync(0xffffffffu, v[p], o);
            if (lane >= o) v[p] += t;
        }
    }
    if (lane == 31) {
#pragma unroll
        for (int p = 0; p < 5; p++) wsum[p][wid] = v[p];
    }
    __syncthreads();
    if (wid == 0) {
#pragma unroll
        for (int p = 0; p < 5; p++) {
            float w = wsum[p][lane];
#pragma unroll
            for (int o = 1; o < 32; o <<= 1) {
                float t = __shfl_up_sync(0xffffffffu, w, o);
                if (lane >= o) w += t;
            }
            wsum[p][lane] = w;
        }
    }
    __syncthreads();

    float dsum = 0.0f;
#pragma unroll
    for (int p = 0; p < 5; p++) {
        float C = v[p] + (wid > 0 ? wsum[p][wid - 1] : 0.0f);
        dsum += bt.b[p] * Aq[p] * C;
    }
    g_den[bh * S_LEN + s] = dsum;
}

// ---------------------------------------------------------------------------
// Phase 1: per-chunk sums of Tk_p(xk)*v per (b,h,chunk,d)
// ---------------------------------------------------------------------------
__global__ __launch_bounds__(64) void chunk_kernel()
{
    const int blk = blockIdx.x;
    const int c = blk & 15, h = (blk >> 4) & 15, b = blk >> 8;
    const int d = threadIdx.x;

    const float* base = g_qkv + ((size_t)(b * S_LEN + c * CHS)) * (3 * DMODEL)
                        + DMODEL + h * DH + d;
    float kv[5] = {0, 0, 0, 0, 0};
    for (int s = 0; s < CHS; s++) {
        float kval = base[(size_t)s * (3 * DMODEL)];
        float vval = base[(size_t)s * (3 * DMODEL) + DMODEL];
        float t[5];
        cheb5(clampx(kval * 0.125f), t);
#pragma unroll
        for (int p = 0; p < 5; p++) kv[p] += t[p] * vval;
    }
    const int bh = b * H_NUM + h;
#pragma unroll
    for (int p = 0; p < 5; p++)
        g_ckv[(((size_t)bh * 5 + p) * NCH + c) * DH + d] = kv[p];
}

// ---------------------------------------------------------------------------
// Phase 2: exclusive prefix over chunks, in place.
// ---------------------------------------------------------------------------
__global__ void prefix_kernel()
{
    const int t = blockIdx.x * blockDim.x + threadIdx.x;
    if (t >= BATCH * H_NUM * 5 * DH) return;
    const int d = t & 63;
    const int bhp = t >> 6;
    const size_t base = (size_t)bhp * NCH * DH + d;
    float run = 0.0f;
    for (int c = 0; c < NCH; c++) {
        size_t idx = base + (size_t)c * DH;
        float tmp = g_ckv[idx];
        g_ckv[idx] = run;
        run += tmp;
    }
}

// ---------------------------------------------------------------------------
// Phase 3: rescan chunk with exclusive offset; fuse numerator + normalize.
// ---------------------------------------------------------------------------
__global__ __launch_bounds__(64) void final_kernel(Betas bt)
{
    const int blk = blockIdx.x;
    const int c = blk & 15, h = (blk >> 4) & 15, b = blk >> 8;
    const int d = threadIdx.x;
    const int bh = b * H_NUM + h;

    float kv[5];
#pragma unroll
    for (int p = 0; p < 5; p++)
        kv[p] = g_ckv[(((size_t)bh * 5 + p) * NCH + c) * DH + d];

    const float* base = g_qkv + ((size_t)(b * S_LEN + c * CHS)) * (3 * DMODEL) + h * DH + d;
    const float* denb = g_den + bh * S_LEN + c * CHS;
    float* ob = g_attn + ((size_t)(b * S_LEN + c * CHS)) * DMODEL + h * DH + d;

    for (int s = 0; s < CHS; s++) {
        const float* r = base + (size_t)s * (3 * DMODEL);
        float qv = r[0];
        float kval = r[DMODEL];
        float vval = r[2 * DMODEL];

        float tk[5];
        cheb5(clampx(kval * 0.125f), tk);
#pragma unroll
        for (int p = 0; p < 5; p++) kv[p] += tk[p] * vval;

        float tq[5];
        cheb5(clampx(qv * 0.125f), tq);
        float num = 0.0f;
#pragma unroll
        for (int p = 0; p < 5; p++) num += bt.b[p] * tq[p] * kv[p];

        ob[(size_t)s * DMODEL] = num / (denb[s] + 1e-7f);
    }
}

// ---------------------------------------------------------------------------
extern "C" void kernel_launch(void* const* d_in, const int* in_sizes, int n_in,
                              void* d_out, int out_size)
{
    const float* x     = (const float*)d_in[0];   // (2,1024,1024)
    const float* W_in  = (const float*)d_in[1];   // (3072,1024)
    const float* W_out = (const float*)d_in[2];   // (1024,1024)
    float* out = (float*)d_out;                   // (2,1024,1024)

    float *qkv, *attn;
    cudaGetSymbolAddress((void**)&qkv, g_qkv);
    cudaGetSymbolAddress((void**)&attn, g_attn);

    // beta[p] = tail[p+1] / sum(tail[1..5])
    double alpha[6], tail[7];
    tail[6] = 0.0;
    for (int j = 5; j >= 0; j--) {
        alpha[j] = pow((double)(j + 1), -1.5);
        tail[j] = tail[j + 1] + alpha[j];
    }
    double bsum = tail[1] + tail[2] + tail[3] + tail[4] + tail[5];
    Betas bt;
    for (int p = 0; p < 5; p++) bt.b[p] = (float)(tail[p + 1] / bsum);

    const int M = BATCH * S_LEN;   // 2048

    gemm_tf32x3<<<dim3(3 * DMODEL / 128, M / 128), 256>>>(x, W_in, qkv, M, 3 * DMODEL, DMODEL);
    den_kernel<<<BATCH * H_NUM, 1024>>>(bt);
    chunk_kernel<<<BATCH * H_NUM * NCH, 64>>>();
    prefix_kernel<<<(BATCH * H_NUM * 5 * DH + 255) / 256, 256>>>();
    final_kernel<<<BATCH * H_NUM * NCH, 64>>>(bt);
    gemm_tf32x3<<<dim3(DMODEL / 128, M / 128), 256>>>(attn, W_out, out, M, DMODEL, DMODEL);
}

// round 4
// speedup vs baseline: 2.3965x; 2.0457x over previous
#include <cuda_runtime.h>
#include <cuda_bf16.h>
#include <cstdint>
#include <cmath>

// Problem constants
#define S_LEN   1024
#define DMODEL  1024
#define H_NUM   16
#define DH      64
#define BATCH   2
#define NCH     16     // chunks along S
#define CHS     64     // chunk length (S_LEN / NCH)

// Scratch (static device globals; no allocation allowed)
__device__ float g_qkv[(size_t)BATCH * S_LEN * 3 * DMODEL];   // 25.2 MB
__device__ float g_attn[(size_t)BATCH * S_LEN * DMODEL];      // 8.4 MB
__device__ float g_den[BATCH * H_NUM * S_LEN];                // 128 KB
__device__ float g_ckv[BATCH * H_NUM * 5 * NCH * DH];         // 640 KB

struct Betas { float b[5]; };

__device__ __forceinline__ float clampx(float x) {
    return fminf(fmaxf(x, -1.0f + 1e-6f), 1.0f - 1e-6f);
}

// Chebyshev T1..T5 (T0=1 implicit; betas for p=0 and p>=6 are exactly zero)
__device__ __forceinline__ void cheb5(float x, float t[5]) {
    float x2 = x + x;
    float t1 = x;
    float t2 = x2 * t1 - 1.0f;
    float t3 = x2 * t2 - t1;
    float t4 = x2 * t3 - t2;
    float t5 = x2 * t4 - t3;
    t[0] = t1; t[1] = t2; t[2] = t3; t[3] = t4; t[4] = t5;
}

// ---------------------------------------------------------------------------
// bf16 split helpers
// ---------------------------------------------------------------------------
__device__ __forceinline__ unsigned pack2(__nv_bfloat16 a, __nv_bfloat16 b) {
    __nv_bfloat162 t(a, b);
    return *reinterpret_cast<unsigned*>(&t);
}

__device__ __forceinline__ void ldsm4(unsigned& r0, unsigned& r1, unsigned& r2, unsigned& r3,
                                      unsigned addr) {
    asm volatile("ldmatrix.sync.aligned.m8n8.x4.shared.b16 {%0,%1,%2,%3}, [%4];"
                 : "=r"(r0), "=r"(r1), "=r"(r2), "=r"(r3) : "r"(addr));
}

__device__ __forceinline__ void mma_bf16(float c[4],
                                         unsigned a0, unsigned a1, unsigned a2, unsigned a3,
                                         unsigned b0, unsigned b1) {
    asm volatile(
        "mma.sync.aligned.m16n8k16.row.col.f32.bf16.bf16.f32 "
        "{%0,%1,%2,%3}, {%4,%5,%6,%7}, {%8,%9}, {%0,%1,%2,%3};"
        : "+f"(c[0]), "+f"(c[1]), "+f"(c[2]), "+f"(c[3])
        : "r"(a0), "r"(a1), "r"(a2), "r"(a3), "r"(b0), "r"(b1));
}

// swizzled byte offset inside a 128x32 bf16 tile (64B rows).
// 16B-chunk column XORed with ((m>>1)&3) -> each 8-row group hits 8 distinct banks.
__device__ __forceinline__ unsigned swz(int m, int cbyte) {
    return (unsigned)((m << 6) + (cbyte ^ (((m >> 1) & 3) << 4)));
}

// ---------------------------------------------------------------------------
// bf16x3 tensor-core GEMM: C[M,N] = A[M,K] @ B[N,K]^T   (row-major)
// BM=BN=128, BK=32, 256 threads (8 warps 2x4), warp tile 64x32.
// hi/lo bf16 split in smem; products hh + hl + lh; ldmatrix fragment loads.
// ---------------------------------------------------------------------------
__global__ __launch_bounds__(256) void gemm_bf16x3(
    const float* __restrict__ A, const float* __restrict__ B,
    float* __restrict__ C, int M, int N, int K)
{
    __shared__ char smem[4 * 8192];   // Ah | Al | Bh | Bl  (128x32 bf16 each)
    char* const Ah = smem;
    char* const Al = smem + 8192;
    char* const Bh = smem + 16384;
    char* const Bl = smem + 24576;

    const int tid  = threadIdx.x;
    const int wid  = tid >> 5;
    const int lane = tid & 31;
    const int wm = (wid >> 2) * 64;   // warp m offset
    const int wn = (wid & 3) * 32;    // warp n offset

    const int bm = blockIdx.y * 128;
    const int bn = blockIdx.x * 128;

    // gmem mapping: float4 index f = tid + i*256 ; row = f>>3, c4 = f&7 (8 float4/row)
    float4 av[4], bv[4];
    const float* Ag[4];
    const float* Bg[4];
    int rr[4], cc4[4];
#pragma unroll
    for (int i = 0; i < 4; i++) {
        int f = tid + i * 256;
        rr[i]  = f >> 3;
        cc4[i] = f & 7;
        Ag[i] = A + (size_t)(bm + rr[i]) * K + cc4[i] * 4;
        Bg[i] = B + (size_t)(bn + rr[i]) * K + cc4[i] * 4;
        av[i] = *(const float4*)Ag[i];
        bv[i] = *(const float4*)Bg[i];
    }

    float acc[4][4][4];
#pragma unroll
    for (int i = 0; i < 4; i++)
#pragma unroll
        for (int j = 0; j < 4; j++)
#pragma unroll
            for (int r = 0; r < 4; r++) acc[i][j][r] = 0.0f;

    // precompute ldmatrix shared addresses (per lane)
    const int lt = lane >> 3, lr = lane & 7;
    unsigned a_base[4], b_base[2];
#pragma unroll
    for (int mf = 0; mf < 4; mf++) {
        int m = wm + mf * 16 + (lt & 1) * 8 + lr;
        a_base[mf] = swz(m, (lt >> 1) * 16);
    }
#pragma unroll
    for (int np = 0; np < 2; np++) {
        int n = wn + np * 16 + (lt >> 1) * 8 + lr;
        b_base[np] = swz(n, (lt & 1) * 16);
    }
    const unsigned sAh = (unsigned)__cvta_generic_to_shared(Ah);
    const unsigned sAl = (unsigned)__cvta_generic_to_shared(Al);
    const unsigned sBh = (unsigned)__cvta_generic_to_shared(Bh);
    const unsigned sBl = (unsigned)__cvta_generic_to_shared(Bl);

    for (int k0 = 0; k0 < K; k0 += 32) {
        __syncthreads();
        // split + store to smem
#pragma unroll
        for (int i = 0; i < 4; i++) {
            const float va[4] = {av[i].x, av[i].y, av[i].z, av[i].w};
            const float vb[4] = {bv[i].x, bv[i].y, bv[i].z, bv[i].w};
            __nv_bfloat16 ha[4], la[4], hb[4], lb[4];
#pragma unroll
            for (int j = 0; j < 4; j++) {
                ha[j] = __float2bfloat16(va[j]);
                la[j] = __float2bfloat16(va[j] - __bfloat162float(ha[j]));
                hb[j] = __float2bfloat16(vb[j]);
                lb[j] = __float2bfloat16(vb[j] - __bfloat162float(hb[j]));
            }
            unsigned off = swz(rr[i], cc4[i] * 8);
            *(uint2*)(Ah + off) = make_uint2(pack2(ha[0], ha[1]), pack2(ha[2], ha[3]));
            *(uint2*)(Al + off) = make_uint2(pack2(la[0], la[1]), pack2(la[2], la[3]));
            *(uint2*)(Bh + off) = make_uint2(pack2(hb[0], hb[1]), pack2(hb[2], hb[3]));
            *(uint2*)(Bl + off) = make_uint2(pack2(lb[0], lb[1]), pack2(lb[2], lb[3]));
        }
        __syncthreads();

        // prefetch next gmem tile
        if (k0 + 32 < K) {
#pragma unroll
            for (int i = 0; i < 4; i++) {
                av[i] = *(const float4*)(Ag[i] + k0 + 32);
                bv[i] = *(const float4*)(Bg[i] + k0 + 32);
            }
        }

#pragma unroll
        for (int kk = 0; kk < 2; kk++) {
            // NOTE: k-step advance is XOR 32 (bit 5 is inside the swizzle field;
            // '+32' would carry into the row bits for swizzled lanes).
            const unsigned kb = kk * 32;
            unsigned ah[4][4], al[4][4];
#pragma unroll
            for (int mf = 0; mf < 4; mf++) {
                ldsm4(ah[mf][0], ah[mf][1], ah[mf][2], ah[mf][3], sAh + (a_base[mf] ^ kb));
                ldsm4(al[mf][0], al[mf][1], al[mf][2], al[mf][3], sAl + (a_base[mf] ^ kb));
            }
            unsigned bhf[4][2], blf[4][2];
#pragma unroll
            for (int np = 0; np < 2; np++) {
                ldsm4(bhf[2 * np][0], bhf[2 * np][1], bhf[2 * np + 1][0], bhf[2 * np + 1][1],
                      sBh + (b_base[np] ^ kb));
                ldsm4(blf[2 * np][0], blf[2 * np][1], blf[2 * np + 1][0], blf[2 * np + 1][1],
                      sBl + (b_base[np] ^ kb));
            }
#pragma unroll
            for (int mf = 0; mf < 4; mf++)
#pragma unroll
                for (int nf = 0; nf < 4; nf++) {
                    mma_bf16(acc[mf][nf], ah[mf][0], ah[mf][1], ah[mf][2], ah[mf][3],
                             bhf[nf][0], bhf[nf][1]);
                    mma_bf16(acc[mf][nf], ah[mf][0], ah[mf][1], ah[mf][2], ah[mf][3],
                             blf[nf][0], blf[nf][1]);
                    mma_bf16(acc[mf][nf], al[mf][0], al[mf][1], al[mf][2], al[mf][3],
                             bhf[nf][0], bhf[nf][1]);
                }
        }
    }

    // epilogue: lane g=lane>>2 rows, th=lane&3 col pairs
    const int g = lane >> 2, th = lane & 3;
#pragma unroll
    for (int mf = 0; mf < 4; mf++) {
#pragma unroll
        for (int nf = 0; nf < 4; nf++) {
            int row = bm + wm + mf * 16 + g;
            int col = bn + wn + nf * 8 + 2 * th;
            *(float2*)(C + (size_t)row * N + col) =
                make_float2(acc[mf][nf][0], acc[mf][nf][1]);
            *(float2*)(C + (size_t)(row + 8) * N + col) =
                make_float2(acc[mf][nf][2], acc[mf][nf][3]);
        }
    }
}

// ---------------------------------------------------------------------------
// den kernel: one block per (b,h), one thread per s.
// ---------------------------------------------------------------------------
__global__ __launch_bounds__(1024) void den_kernel(Betas bt)
{
    const int bh = blockIdx.x;            // 0..31
    const int b = bh >> 4, h = bh & 15;
    const int s = threadIdx.x;

    const float* qrow = g_qkv + ((size_t)(b * S_LEN + s)) * (3 * DMODEL) + h * DH;

    float Aq[5] = {0, 0, 0, 0, 0};
    float Rk[5] = {0, 0, 0, 0, 0};
#pragma unroll 4
    for (int d = 0; d < DH; d++) {
        float tq[5], tk[5];
        cheb5(clampx(qrow[d] * 0.125f), tq);
        cheb5(clampx(qrow[DMODEL + d] * 0.125f), tk);
#pragma unroll
        for (int p = 0; p < 5; p++) { Aq[p] += tq[p]; Rk[p] += tk[p]; }
    }

    const int lane = s & 31, wid = s >> 5;
    __shared__ float wsum[5][32];

    float v[5];
#pragma unroll
    for (int p = 0; p < 5; p++) v[p] = Rk[p];
#pragma unroll
    for (int p = 0; p < 5; p++) {
#pragma unroll
        for (int o = 1; o < 32; o <<= 1) {
            float t = __shfl_up_sync(0xffffffffu, v[p], o);
            if (lane >= o) v[p] += t;
        }
    }
    if (lane == 31) {
#pragma unroll
        for (int p = 0; p < 5; p++) wsum[p][wid] = v[p];
    }
    __syncthreads();
    if (wid == 0) {
#pragma unroll
        for (int p = 0; p < 5; p++) {
            float w = wsum[p][lane];
#pragma unroll
            for (int o = 1; o < 32; o <<= 1) {
                float t = __shfl_up_sync(0xffffffffu, w, o);
                if (lane >= o) w += t;
            }
            wsum[p][lane] = w;
        }
    }
    __syncthreads();

    float dsum = 0.0f;
#pragma unroll
    for (int p = 0; p < 5; p++) {
        float C = v[p] + (wid > 0 ? wsum[p][wid - 1] : 0.0f);
        dsum += bt.b[p] * Aq[p] * C;
    }
    g_den[bh * S_LEN + s] = dsum;
}

// ---------------------------------------------------------------------------
// Phase 1: per-chunk sums of Tk_p(xk)*v per (b,h,chunk,d)
// ---------------------------------------------------------------------------
__global__ __launch_bounds__(64) void chunk_kernel()
{
    const int blk = blockIdx.x;
    const int c = blk & 15, h = (blk >> 4) & 15, b = blk >> 8;
    const int d = threadIdx.x;

    const float* base = g_qkv + ((size_t)(b * S_LEN + c * CHS)) * (3 * DMODEL)
                        + DMODEL + h * DH + d;
    float kv[5] = {0, 0, 0, 0, 0};
    for (int s = 0; s < CHS; s++) {
        float kval = base[(size_t)s * (3 * DMODEL)];
        float vval = base[(size_t)s * (3 * DMODEL) + DMODEL];
        float t[5];
        cheb5(clampx(kval * 0.125f), t);
#pragma unroll
        for (int p = 0; p < 5; p++) kv[p] += t[p] * vval;
    }
    const int bh = b * H_NUM + h;
#pragma unroll
    for (int p = 0; p < 5; p++)
        g_ckv[(((size_t)bh * 5 + p) * NCH + c) * DH + d] = kv[p];
}

// ---------------------------------------------------------------------------
// Phase 2: exclusive prefix over chunks, in place.
// ---------------------------------------------------------------------------
__global__ void prefix_kernel()
{
    const int t = blockIdx.x * blockDim.x + threadIdx.x;
    if (t >= BATCH * H_NUM * 5 * DH) return;
    const int d = t & 63;
    const int bhp = t >> 6;
    const size_t base = (size_t)bhp * NCH * DH + d;
    float run = 0.0f;
    for (int c = 0; c < NCH; c++) {
        size_t idx = base + (size_t)c * DH;
        float tmp = g_ckv[idx];
        g_ckv[idx] = run;
        run += tmp;
    }
}

// ---------------------------------------------------------------------------
// Phase 3: rescan chunk with exclusive offset; fuse numerator + normalize.
// ---------------------------------------------------------------------------
__global__ __launch_bounds__(64) void final_kernel(Betas bt)
{
    const int blk = blockIdx.x;
    const int c = blk & 15, h = (blk >> 4) & 15, b = blk >> 8;
    const int d = threadIdx.x;
    const int bh = b * H_NUM + h;

    float kv[5];
#pragma unroll
    for (int p = 0; p < 5; p++)
        kv[p] = g_ckv[(((size_t)bh * 5 + p) * NCH + c) * DH + d];

    const float* base = g_qkv + ((size_t)(b * S_LEN + c * CHS)) * (3 * DMODEL) + h * DH + d;
    const float* denb = g_den + bh * S_LEN + c * CHS;
    float* ob = g_attn + ((size_t)(b * S_LEN + c * CHS)) * DMODEL + h * DH + d;

    for (int s = 0; s < CHS; s++) {
        const float* r = base + (size_t)s * (3 * DMODEL);
        float qv = r[0];
        float kval = r[DMODEL];
        float vval = r[2 * DMODEL];

        float tk[5];
        cheb5(clampx(kval * 0.125f), tk);
#pragma unroll
        for (int p = 0; p < 5; p++) kv[p] += tk[p] * vval;

        float tq[5];
        cheb5(clampx(qv * 0.125f), tq);
        float num = 0.0f;
#pragma unroll
        for (int p = 0; p < 5; p++) num += bt.b[p] * tq[p] * kv[p];

        ob[(size_t)s * DMODEL] = num / (denb[s] + 1e-7f);
    }
}

// ---------------------------------------------------------------------------
extern "C" void kernel_launch(void* const* d_in, const int* in_sizes, int n_in,
                              void* d_out, int out_size)
{
    const float* x     = (const float*)d_in[0];   // (2,1024,1024)
    const float* W_in  = (const float*)d_in[1];   // (3072,1024)
    const float* W_out = (const float*)d_in[2];   // (1024,1024)
    float* out = (float*)d_out;                   // (2,1024,1024)

    float *qkv, *attn;
    cudaGetSymbolAddress((void**)&qkv, g_qkv);
    cudaGetSymbolAddress((void**)&attn, g_attn);

    // beta[p] = tail[p+1] / sum(tail[1..5])
    double alpha[6], tail[7];
    tail[6] = 0.0;
    for (int j = 5; j >= 0; j--) {
        alpha[j] = pow((double)(j + 1), -1.5);
        tail[j] = tail[j + 1] + alpha[j];
    }
    double bsum = tail[1] + tail[2] + tail[3] + tail[4] + tail[5];
    Betas bt;
    for (int p = 0; p < 5; p++) bt.b[p] = (float)(tail[p + 1] / bsum);

    const int M = BATCH * S_LEN;   // 2048

    gemm_bf16x3<<<dim3(3 * DMODEL / 128, M / 128), 256>>>(x, W_in, qkv, M, 3 * DMODEL, DMODEL);
    den_kernel<<<BATCH * H_NUM, 1024>>>(bt);
    chunk_kernel<<<BATCH * H_NUM * NCH, 64>>>();
    prefix_kernel<<<(BATCH * H_NUM * 5 * DH + 255) / 256, 256>>>();
    final_kernel<<<BATCH * H_NUM * NCH, 64>>>(bt);
    gemm_bf16x3<<<dim3(DMODEL / 128, M / 128), 256>>>(attn, W_out, out, M, DMODEL, DMODEL);
}

// round 5
// speedup vs baseline: 2.4240x; 1.0115x over previous
#include <cuda_runtime.h>
#include <cuda_bf16.h>
#include <cstdint>
#include <cmath>

// Problem constants
#define S_LEN   1024
#define DMODEL  1024
#define H_NUM   16
#define DH      64
#define BATCH   2
#define NCH     16     // chunks along S
#define CHS     64     // chunk length (S_LEN / NCH)

// Scratch (static device globals; no allocation allowed)
__device__ float g_qkv[(size_t)BATCH * S_LEN * 3 * DMODEL];   // 25.2 MB
__device__ float g_den[BATCH * H_NUM * S_LEN];                // 128 KB
__device__ float g_ckv[BATCH * H_NUM * 5 * NCH * DH];         // 640 KB

// bf16 hi/lo split operands
__device__ __nv_bfloat16 g_xh[(size_t)BATCH * S_LEN * DMODEL];
__device__ __nv_bfloat16 g_xl[(size_t)BATCH * S_LEN * DMODEL];
__device__ __nv_bfloat16 g_wih[(size_t)3 * DMODEL * DMODEL];
__device__ __nv_bfloat16 g_wil[(size_t)3 * DMODEL * DMODEL];
__device__ __nv_bfloat16 g_woh[(size_t)DMODEL * DMODEL];
__device__ __nv_bfloat16 g_wol[(size_t)DMODEL * DMODEL];
__device__ __nv_bfloat16 g_ath[(size_t)BATCH * S_LEN * DMODEL];
__device__ __nv_bfloat16 g_atl[(size_t)BATCH * S_LEN * DMODEL];

struct Betas { float b[5]; };

__device__ __forceinline__ float clampx(float x) {
    return fminf(fmaxf(x, -1.0f + 1e-6f), 1.0f - 1e-6f);
}

// Chebyshev T1..T5 (T0=1 implicit; betas for p=0 and p>=6 are exactly zero)
__device__ __forceinline__ void cheb5(float x, float t[5]) {
    float x2 = x + x;
    float t1 = x;
    float t2 = x2 * t1 - 1.0f;
    float t3 = x2 * t2 - t1;
    float t4 = x2 * t3 - t2;
    float t5 = x2 * t4 - t3;
    t[0] = t1; t[1] = t2; t[2] = t3; t[3] = t4; t[4] = t5;
}

__device__ __forceinline__ unsigned pack2(__nv_bfloat16 a, __nv_bfloat16 b) {
    __nv_bfloat162 t(a, b);
    return *reinterpret_cast<unsigned*>(&t);
}

__device__ __forceinline__ void ldsm4(unsigned& r0, unsigned& r1, unsigned& r2, unsigned& r3,
                                      unsigned addr) {
    asm volatile("ldmatrix.sync.aligned.m8n8.x4.shared.b16 {%0,%1,%2,%3}, [%4];"
                 : "=r"(r0), "=r"(r1), "=r"(r2), "=r"(r3) : "r"(addr));
}

__device__ __forceinline__ void mma_bf16(float c[4],
                                         unsigned a0, unsigned a1, unsigned a2, unsigned a3,
                                         unsigned b0, unsigned b1) {
    asm volatile(
        "mma.sync.aligned.m16n8k16.row.col.f32.bf16.bf16.f32 "
        "{%0,%1,%2,%3}, {%4,%5,%6,%7}, {%8,%9}, {%0,%1,%2,%3};"
        : "+f"(c[0]), "+f"(c[1]), "+f"(c[2]), "+f"(c[3])
        : "r"(a0), "r"(a1), "r"(a2), "r"(a3), "r"(b0), "r"(b1));
}

#define CP16(dst, src) \
    asm volatile("cp.async.cg.shared.global [%0], [%1], 16;" :: "r"(dst), "l"(src))
#define CP_COMMIT() asm volatile("cp.async.commit_group;")
#define CP_WAIT1()  asm volatile("cp.async.wait_group 1;")
#define CP_WAIT0()  asm volatile("cp.async.wait_group 0;")

// swizzled byte offset inside a 128x32 bf16 tile (64B rows).
__device__ __forceinline__ unsigned swz(int m, int cbyte) {
    return (unsigned)((m << 6) + (cbyte ^ (((m >> 1) & 3) << 4)));
}

// ---------------------------------------------------------------------------
// split3: f32 -> bf16 hi + bf16 lo residual, three tensors in one launch
// ---------------------------------------------------------------------------
__global__ __launch_bounds__(256) void split3(
    const float* __restrict__ a, __nv_bfloat16* __restrict__ ah, __nv_bfloat16* __restrict__ al, int na,
    const float* __restrict__ b, __nv_bfloat16* __restrict__ bh, __nv_bfloat16* __restrict__ bl, int nb,
    const float* __restrict__ c, __nv_bfloat16* __restrict__ ch, __nv_bfloat16* __restrict__ cl, int nc)
{
    int i = (blockIdx.x * blockDim.x + threadIdx.x) * 4;
    const float* src; __nv_bfloat16 *hi, *lo; int off;
    if (i < na)           { src = a; hi = ah; lo = al; off = i; }
    else if (i < na + nb) { src = b; hi = bh; lo = bl; off = i - na; }
    else if (i < na + nb + nc) { src = c; hi = ch; lo = cl; off = i - na - nb; }
    else return;

    float4 v = *(const float4*)(src + off);
    __nv_bfloat16 h0 = __float2bfloat16(v.x), h1 = __float2bfloat16(v.y);
    __nv_bfloat16 h2 = __float2bfloat16(v.z), h3 = __float2bfloat16(v.w);
    __nv_bfloat16 l0 = __float2bfloat16(v.x - __bfloat162float(h0));
    __nv_bfloat16 l1 = __float2bfloat16(v.y - __bfloat162float(h1));
    __nv_bfloat16 l2 = __float2bfloat16(v.z - __bfloat162float(h2));
    __nv_bfloat16 l3 = __float2bfloat16(v.w - __bfloat162float(h3));
    *(uint2*)(hi + off) = make_uint2(pack2(h0, h1), pack2(h2, h3));
    *(uint2*)(lo + off) = make_uint2(pack2(l0, l1), pack2(l2, l3));
}

// ---------------------------------------------------------------------------
// bf16x3 GEMM, pre-split operands, cp.async double buffer:
//   C[M,N] = (Ah+Al)[M,K] @ (Bh+Bl)[N,K]^T  (drop Al*Bl)
// BM=BN=128, BK=32, 256 threads (8 warps 2x4), warp tile 64x32.
// Dynamic smem: 2 stages x 32KB (Ah|Al|Bh|Bl, 8KB each).
// ---------------------------------------------------------------------------
__global__ __launch_bounds__(256) void gemm_split(
    const __nv_bfloat16* __restrict__ Ahg, const __nv_bfloat16* __restrict__ Alg,
    const __nv_bfloat16* __restrict__ Bhg, const __nv_bfloat16* __restrict__ Blg,
    float* __restrict__ C, int M, int N, int K)
{
    extern __shared__ char dsmem[];
    const unsigned smem_u32 = (unsigned)__cvta_generic_to_shared(dsmem);

    const int tid  = threadIdx.x;
    const int wid  = tid >> 5;
    const int lane = tid & 31;
    const int wm = (wid >> 2) * 64;
    const int wn = (wid & 3) * 32;

    const int bm = blockIdx.y * 128;
    const int bn = blockIdx.x * 128;

    // copy mapping: chunk c = tid + i*256 (512 chunks of 16B per buffer)
    int crow[2], ccb[2];
    size_t aoff[2], boff[2];     // gmem byte offsets excluding k (elements*2)
    unsigned dsw[2];
#pragma unroll
    for (int i = 0; i < 2; i++) {
        int c = tid + i * 256;
        crow[i] = c >> 2;
        ccb[i]  = (c & 3) * 16;
        aoff[i] = (size_t)(bm + crow[i]) * K * 2 + ccb[i];
        boff[i] = (size_t)(bn + crow[i]) * K * 2 + ccb[i];
        dsw[i]  = swz(crow[i], ccb[i]);
    }
    const char* Ahc = (const char*)Ahg;
    const char* Alc = (const char*)Alg;
    const char* Bhc = (const char*)Bhg;
    const char* Blc = (const char*)Blg;

    auto issue_stage = [&](int stg, int k0) {
        unsigned sb = smem_u32 + (unsigned)stg * 32768u;
        size_t kb = (size_t)k0 * 2;
#pragma unroll
        for (int i = 0; i < 2; i++) {
            unsigned d = sb + dsw[i];
            CP16(d,          Ahc + aoff[i] + kb);
            CP16(d + 8192u,  Alc + aoff[i] + kb);
            CP16(d + 16384u, Bhc + boff[i] + kb);
            CP16(d + 24576u, Blc + boff[i] + kb);
        }
        CP_COMMIT();
    };

    float acc[4][4][4];
#pragma unroll
    for (int i = 0; i < 4; i++)
#pragma unroll
        for (int j = 0; j < 4; j++)
#pragma unroll
            for (int r = 0; r < 4; r++) acc[i][j][r] = 0.0f;

    // ldmatrix addresses (relative to buffer base)
    const int lt = lane >> 3, lr = lane & 7;
    unsigned a_base[4], b_base[2];
#pragma unroll
    for (int mf = 0; mf < 4; mf++) {
        int m = wm + mf * 16 + (lt & 1) * 8 + lr;
        a_base[mf] = swz(m, (lt >> 1) * 16);
    }
#pragma unroll
    for (int np = 0; np < 2; np++) {
        int n = wn + np * 16 + (lt >> 1) * 8 + lr;
        b_base[np] = swz(n, (lt & 1) * 16);
    }

    const int nk = K / 32;
    issue_stage(0, 0);

    for (int kt = 0; kt < nk; kt++) {
        const int cur = kt & 1;
        if (kt + 1 < nk) { issue_stage(cur ^ 1, (kt + 1) * 32); CP_WAIT1(); }
        else             { CP_WAIT0(); }
        __syncthreads();

        const unsigned st = smem_u32 + (unsigned)cur * 32768u;
        const unsigned sAh = st, sAl = st + 8192u, sBh = st + 16384u, sBl = st + 24576u;

#pragma unroll
        for (int kk = 0; kk < 2; kk++) {
            const unsigned kb = kk * 32;   // XOR advance (bit 5 within swizzle field)
            unsigned ah[4][4], al[4][4];
#pragma unroll
            for (int mf = 0; mf < 4; mf++) {
                ldsm4(ah[mf][0], ah[mf][1], ah[mf][2], ah[mf][3], sAh + (a_base[mf] ^ kb));
                ldsm4(al[mf][0], al[mf][1], al[mf][2], al[mf][3], sAl + (a_base[mf] ^ kb));
            }
            unsigned bhf[4][2], blf[4][2];
#pragma unroll
            for (int np = 0; np < 2; np++) {
                ldsm4(bhf[2 * np][0], bhf[2 * np][1], bhf[2 * np + 1][0], bhf[2 * np + 1][1],
                      sBh + (b_base[np] ^ kb));
                ldsm4(blf[2 * np][0], blf[2 * np][1], blf[2 * np + 1][0], blf[2 * np + 1][1],
                      sBl + (b_base[np] ^ kb));
            }
#pragma unroll
            for (int mf = 0; mf < 4; mf++)
#pragma unroll
                for (int nf = 0; nf < 4; nf++) {
                    mma_bf16(acc[mf][nf], ah[mf][0], ah[mf][1], ah[mf][2], ah[mf][3],
                             bhf[nf][0], bhf[nf][1]);
                    mma_bf16(acc[mf][nf], ah[mf][0], ah[mf][1], ah[mf][2], ah[mf][3],
                             blf[nf][0], blf[nf][1]);
                    mma_bf16(acc[mf][nf], al[mf][0], al[mf][1], al[mf][2], al[mf][3],
                             bhf[nf][0], bhf[nf][1]);
                }
        }
        __syncthreads();
    }

    const int g = lane >> 2, th = lane & 3;
#pragma unroll
    for (int mf = 0; mf < 4; mf++) {
#pragma unroll
        for (int nf = 0; nf < 4; nf++) {
            int row = bm + wm + mf * 16 + g;
            int col = bn + wn + nf * 8 + 2 * th;
            *(float2*)(C + (size_t)row * N + col) =
                make_float2(acc[mf][nf][0], acc[mf][nf][1]);
            *(float2*)(C + (size_t)(row + 8) * N + col) =
                make_float2(acc[mf][nf][2], acc[mf][nf][3]);
        }
    }
}

// ---------------------------------------------------------------------------
// den kernel: one block per (b,h), one thread per s.
// ---------------------------------------------------------------------------
__global__ __launch_bounds__(1024) void den_kernel(Betas bt)
{
    const int bh = blockIdx.x;            // 0..31
    const int b = bh >> 4, h = bh & 15;
    const int s = threadIdx.x;

    const float* qrow = g_qkv + ((size_t)(b * S_LEN + s)) * (3 * DMODEL) + h * DH;

    float Aq[5] = {0, 0, 0, 0, 0};
    float Rk[5] = {0, 0, 0, 0, 0};
#pragma unroll 4
    for (int d = 0; d < DH; d++) {
        float tq[5], tk[5];
        cheb5(clampx(qrow[d] * 0.125f), tq);
        cheb5(clampx(qrow[DMODEL + d] * 0.125f), tk);
#pragma unroll
        for (int p = 0; p < 5; p++) { Aq[p] += tq[p]; Rk[p] += tk[p]; }
    }

    const int lane = s & 31, wid = s >> 5;
    __shared__ float wsum[5][32];

    float v[5];
#pragma unroll
    for (int p = 0; p < 5; p++) v[p] = Rk[p];
#pragma unroll
    for (int p = 0; p < 5; p++) {
#pragma unroll
        for (int o = 1; o < 32; o <<= 1) {
            float t = __shfl_up_sync(0xffffffffu, v[p], o);
            if (lane >= o) v[p] += t;
        }
    }
    if (lane == 31) {
#pragma unroll
        for (int p = 0; p < 5; p++) wsum[p][wid] = v[p];
    }
    __syncthreads();
    if (wid == 0) {
#pragma unroll
        for (int p = 0; p < 5; p++) {
            float w = wsum[p][lane];
#pragma unroll
            for (int o = 1; o < 32; o <<= 1) {
                float t = __shfl_up_sync(0xffffffffu, w, o);
                if (lane >= o) w += t;
            }
            wsum[p][lane] = w;
        }
    }
    __syncthreads();

    float dsum = 0.0f;
#pragma unroll
    for (int p = 0; p < 5; p++) {
        float C = v[p] + (wid > 0 ? wsum[p][wid - 1] : 0.0f);
        dsum += bt.b[p] * Aq[p] * C;
    }
    g_den[bh * S_LEN + s] = dsum;
}

// ---------------------------------------------------------------------------
// Phase 1: per-chunk sums of Tk_p(xk)*v per (b,h,chunk,d)
// ---------------------------------------------------------------------------
__global__ __launch_bounds__(64) void chunk_kernel()
{
    const int blk = blockIdx.x;
    const int c = blk & 15, h = (blk >> 4) & 15, b = blk >> 8;
    const int d = threadIdx.x;

    const float* base = g_qkv + ((size_t)(b * S_LEN + c * CHS)) * (3 * DMODEL)
                        + DMODEL + h * DH + d;
    float kv[5] = {0, 0, 0, 0, 0};
    for (int s = 0; s < CHS; s++) {
        float kval = base[(size_t)s * (3 * DMODEL)];
        float vval = base[(size_t)s * (3 * DMODEL) + DMODEL];
        float t[5];
        cheb5(clampx(kval * 0.125f), t);
#pragma unroll
        for (int p = 0; p < 5; p++) kv[p] += t[p] * vval;
    }
    const int bh = b * H_NUM + h;
#pragma unroll
    for (int p = 0; p < 5; p++)
        g_ckv[(((size_t)bh * 5 + p) * NCH + c) * DH + d] = kv[p];
}

// ---------------------------------------------------------------------------
// Phase 2: exclusive prefix over chunks, in place.
// ---------------------------------------------------------------------------
__global__ void prefix_kernel()
{
    const int t = blockIdx.x * blockDim.x + threadIdx.x;
    if (t >= BATCH * H_NUM * 5 * DH) return;
    const int d = t & 63;
    const int bhp = t >> 6;
    const size_t base = (size_t)bhp * NCH * DH + d;
    float run = 0.0f;
    for (int c = 0; c < NCH; c++) {
        size_t idx = base + (size_t)c * DH;
        float tmp = g_ckv[idx];
        g_ckv[idx] = run;
        run += tmp;
    }
}

// ---------------------------------------------------------------------------
// Phase 3: rescan chunk; fuse numerator + normalize; emit bf16 hi/lo for GEMM2.
// ---------------------------------------------------------------------------
__global__ __launch_bounds__(64) void final_kernel(Betas bt)
{
    const int blk = blockIdx.x;
    const int c = blk & 15, h = (blk >> 4) & 15, b = blk >> 8;
    const int d = threadIdx.x;
    const int bh = b * H_NUM + h;

    float kv[5];
#pragma unroll
    for (int p = 0; p < 5; p++)
        kv[p] = g_ckv[(((size_t)bh * 5 + p) * NCH + c) * DH + d];

    const float* base = g_qkv + ((size_t)(b * S_LEN + c * CHS)) * (3 * DMODEL) + h * DH + d;
    const float* denb = g_den + bh * S_LEN + c * CHS;
    const size_t obase = ((size_t)(b * S_LEN + c * CHS)) * DMODEL + h * DH + d;

    for (int s = 0; s < CHS; s++) {
        const float* r = base + (size_t)s * (3 * DMODEL);
        float qv = r[0];
        float kval = r[DMODEL];
        float vval = r[2 * DMODEL];

        float tk[5];
        cheb5(clampx(kval * 0.125f), tk);
#pragma unroll
        for (int p = 0; p < 5; p++) kv[p] += tk[p] * vval;

        float tq[5];
        cheb5(clampx(qv * 0.125f), tq);
        float num = 0.0f;
#pragma unroll
        for (int p = 0; p < 5; p++) num += bt.b[p] * tq[p] * kv[p];

        float res = num / (denb[s] + 1e-7f);
        __nv_bfloat16 hi = __float2bfloat16(res);
        size_t idx = obase + (size_t)s * DMODEL;
        g_ath[idx] = hi;
        g_atl[idx] = __float2bfloat16(res - __bfloat162float(hi));
    }
}

// ---------------------------------------------------------------------------
extern "C" void kernel_launch(void* const* d_in, const int* in_sizes, int n_in,
                              void* d_out, int out_size)
{
    const float* x     = (const float*)d_in[0];   // (2,1024,1024)
    const float* W_in  = (const float*)d_in[1];   // (3072,1024)
    const float* W_out = (const float*)d_in[2];   // (1024,1024)
    float* out = (float*)d_out;                   // (2,1024,1024)

    float* qkv;
    cudaGetSymbolAddress((void**)&qkv, g_qkv);
    __nv_bfloat16 *xh, *xl, *wih, *wil, *woh, *wol, *ath, *atl;
    cudaGetSymbolAddress((void**)&xh,  g_xh);
    cudaGetSymbolAddress((void**)&xl,  g_xl);
    cudaGetSymbolAddress((void**)&wih, g_wih);
    cudaGetSymbolAddress((void**)&wil, g_wil);
    cudaGetSymbolAddress((void**)&woh, g_woh);
    cudaGetSymbolAddress((void**)&wol, g_wol);
    cudaGetSymbolAddress((void**)&ath, g_ath);
    cudaGetSymbolAddress((void**)&atl, g_atl);

    // beta[p] = tail[p+1] / sum(tail[1..5])
    double alpha[6], tail[7];
    tail[6] = 0.0;
    for (int j = 5; j >= 0; j--) {
        alpha[j] = pow((double)(j + 1), -1.5);
        tail[j] = tail[j + 1] + alpha[j];
    }
    double bsum = tail[1] + tail[2] + tail[3] + tail[4] + tail[5];
    Betas bt;
    for (int p = 0; p < 5; p++) bt.b[p] = (float)(tail[p + 1] / bsum);

    const int M = BATCH * S_LEN;           // 2048
    const int nx = M * DMODEL;             // 2M
    const int nw1 = 3 * DMODEL * DMODEL;   // 3M
    const int nw2 = DMODEL * DMODEL;       // 1M

    static bool attr_set = false;
    if (!attr_set) {
        cudaFuncSetAttribute(gemm_split, cudaFuncAttributeMaxDynamicSharedMemorySize, 65536);
        attr_set = true;
    }

    split3<<<(nx + nw1 + nw2) / 4 / 256, 256>>>(x, xh, xl, nx,
                                                W_in, wih, wil, nw1,
                                                W_out, woh, wol, nw2);
    gemm_split<<<dim3(3 * DMODEL / 128, M / 128), 256, 65536>>>(
        xh, xl, wih, wil, qkv, M, 3 * DMODEL, DMODEL);
    den_kernel<<<BATCH * H_NUM, 1024>>>(bt);
    chunk_kernel<<<BATCH * H_NUM * NCH, 64>>>();
    prefix_kernel<<<(BATCH * H_NUM * 5 * DH + 255) / 256, 256>>>();
    final_kernel<<<BATCH * H_NUM * NCH, 64>>>(bt);
    gemm_split<<<dim3(DMODEL / 128, M / 128), 256, 65536>>>(
        ath, atl, woh, wol, out, M, DMODEL, DMODEL);
}

// round 6
// speedup vs baseline: 3.5080x; 1.4472x over previous
#include <cuda_runtime.h>
#include <cuda_bf16.h>
#include <cstdint>
#include <cmath>

// Problem constants
#define S_LEN   1024
#define DMODEL  1024
#define H_NUM   16
#define DH      64
#define BATCH   2
#define NCH     32     // chunks along S
#define CHS     32     // chunk length (S_LEN / NCH)

// Scratch (static device globals; no allocation allowed)
__device__ float g_qkv[(size_t)BATCH * S_LEN * 3 * DMODEL];   // 25.2 MB
__device__ float g_den[BATCH * H_NUM * S_LEN];                // 128 KB
__device__ float g_ckv[BATCH * H_NUM * 5 * NCH * DH];         // kv chunk sums -> exclusive prefix
__device__ float g_crk[BATCH * H_NUM * 5 * NCH];              // rk chunk sums -> exclusive prefix

// bf16 hi/lo split operands
__device__ __nv_bfloat16 g_xh[(size_t)BATCH * S_LEN * DMODEL];
__device__ __nv_bfloat16 g_xl[(size_t)BATCH * S_LEN * DMODEL];
__device__ __nv_bfloat16 g_wih[(size_t)3 * DMODEL * DMODEL];
__device__ __nv_bfloat16 g_wil[(size_t)3 * DMODEL * DMODEL];
__device__ __nv_bfloat16 g_woh[(size_t)DMODEL * DMODEL];
__device__ __nv_bfloat16 g_wol[(size_t)DMODEL * DMODEL];
__device__ __nv_bfloat16 g_ath[(size_t)BATCH * S_LEN * DMODEL];
__device__ __nv_bfloat16 g_atl[(size_t)BATCH * S_LEN * DMODEL];

struct Betas { float b[5]; };

__device__ __forceinline__ float clampx(float x) {
    return fminf(fmaxf(x, -1.0f + 1e-6f), 1.0f - 1e-6f);
}

__device__ __forceinline__ void cheb5(float x, float t[5]) {
    float x2 = x + x;
    float t1 = x;
    float t2 = x2 * t1 - 1.0f;
    float t3 = x2 * t2 - t1;
    float t4 = x2 * t3 - t2;
    float t5 = x2 * t4 - t3;
    t[0] = t1; t[1] = t2; t[2] = t3; t[3] = t4; t[4] = t5;
}

__device__ __forceinline__ unsigned pack2(__nv_bfloat16 a, __nv_bfloat16 b) {
    __nv_bfloat162 t(a, b);
    return *reinterpret_cast<unsigned*>(&t);
}

__device__ __forceinline__ void ldsm4(unsigned& r0, unsigned& r1, unsigned& r2, unsigned& r3,
                                      unsigned addr) {
    asm volatile("ldmatrix.sync.aligned.m8n8.x4.shared.b16 {%0,%1,%2,%3}, [%4];"
                 : "=r"(r0), "=r"(r1), "=r"(r2), "=r"(r3) : "r"(addr));
}

__device__ __forceinline__ void mma_bf16(float c[4],
                                         unsigned a0, unsigned a1, unsigned a2, unsigned a3,
                                         unsigned b0, unsigned b1) {
    asm volatile(
        "mma.sync.aligned.m16n8k16.row.col.f32.bf16.bf16.f32 "
        "{%0,%1,%2,%3}, {%4,%5,%6,%7}, {%8,%9}, {%0,%1,%2,%3};"
        : "+f"(c[0]), "+f"(c[1]), "+f"(c[2]), "+f"(c[3])
        : "r"(a0), "r"(a1), "r"(a2), "r"(a3), "r"(b0), "r"(b1));
}

#define CP16(dst, src) \
    asm volatile("cp.async.cg.shared.global [%0], [%1], 16;" :: "r"(dst), "l"(src))
#define CP_COMMIT() asm volatile("cp.async.commit_group;")
#define CP_WAIT1()  asm volatile("cp.async.wait_group 1;")
#define CP_WAIT0()  asm volatile("cp.async.wait_group 0;")

// swizzled byte offset inside a 128x32 bf16 tile (64B rows).
__device__ __forceinline__ unsigned swz(int m, int cbyte) {
    return (unsigned)((m << 6) + (cbyte ^ (((m >> 1) & 3) << 4)));
}

// ---------------------------------------------------------------------------
// split3: f32 -> bf16 hi + bf16 lo residual, three tensors in one launch
// ---------------------------------------------------------------------------
__global__ __launch_bounds__(256) void split3(
    const float* __restrict__ a, __nv_bfloat16* __restrict__ ah, __nv_bfloat16* __restrict__ al, int na,
    const float* __restrict__ b, __nv_bfloat16* __restrict__ bh, __nv_bfloat16* __restrict__ bl, int nb,
    const float* __restrict__ c, __nv_bfloat16* __restrict__ ch, __nv_bfloat16* __restrict__ cl, int nc)
{
    int i = (blockIdx.x * blockDim.x + threadIdx.x) * 4;
    const float* src; __nv_bfloat16 *hi, *lo; int off;
    if (i < na)           { src = a; hi = ah; lo = al; off = i; }
    else if (i < na + nb) { src = b; hi = bh; lo = bl; off = i - na; }
    else if (i < na + nb + nc) { src = c; hi = ch; lo = cl; off = i - na - nb; }
    else return;

    float4 v = *(const float4*)(src + off);
    __nv_bfloat16 h0 = __float2bfloat16(v.x), h1 = __float2bfloat16(v.y);
    __nv_bfloat16 h2 = __float2bfloat16(v.z), h3 = __float2bfloat16(v.w);
    __nv_bfloat16 l0 = __float2bfloat16(v.x - __bfloat162float(h0));
    __nv_bfloat16 l1 = __float2bfloat16(v.y - __bfloat162float(h1));
    __nv_bfloat16 l2 = __float2bfloat16(v.z - __bfloat162float(h2));
    __nv_bfloat16 l3 = __float2bfloat16(v.w - __bfloat162float(h3));
    *(uint2*)(hi + off) = make_uint2(pack2(h0, h1), pack2(h2, h3));
    *(uint2*)(lo + off) = make_uint2(pack2(l0, l1), pack2(l2, l3));
}

// ---------------------------------------------------------------------------
// bf16x3 GEMM, pre-split operands, 3-stage cp.async pipeline (1 sync/tile):
//   C[M,N] = (Ah+Al)[M,K] @ (Bh+Bl)[N,K]^T  (drop Al*Bl)
// BM=BN=128, BK=32, 256 threads (8 warps 2x4), warp tile 64x32.
// Dynamic smem: 3 stages x 32KB (Ah|Al|Bh|Bl, 8KB each).
// ---------------------------------------------------------------------------
__global__ __launch_bounds__(256) void gemm_split(
    const __nv_bfloat16* __restrict__ Ahg, const __nv_bfloat16* __restrict__ Alg,
    const __nv_bfloat16* __restrict__ Bhg, const __nv_bfloat16* __restrict__ Blg,
    float* __restrict__ C, int M, int N, int K)
{
    extern __shared__ char dsmem[];
    const unsigned smem_u32 = (unsigned)__cvta_generic_to_shared(dsmem);

    const int tid  = threadIdx.x;
    const int wid  = tid >> 5;
    const int lane = tid & 31;
    const int wm = (wid >> 2) * 64;
    const int wn = (wid & 3) * 32;

    const int bm = blockIdx.y * 128;
    const int bn = blockIdx.x * 128;

    // copy mapping: chunk c = tid + i*256 (512 chunks of 16B per buffer)
    int crow[2], ccb[2];
    size_t aoff[2], boff[2];
    unsigned dsw[2];
#pragma unroll
    for (int i = 0; i < 2; i++) {
        int c = tid + i * 256;
        crow[i] = c >> 2;
        ccb[i]  = (c & 3) * 16;
        aoff[i] = (size_t)(bm + crow[i]) * K * 2 + ccb[i];
        boff[i] = (size_t)(bn + crow[i]) * K * 2 + ccb[i];
        dsw[i]  = swz(crow[i], ccb[i]);
    }
    const char* Ahc = (const char*)Ahg;
    const char* Alc = (const char*)Alg;
    const char* Bhc = (const char*)Bhg;
    const char* Blc = (const char*)Blg;

    auto issue_stage = [&](int stg, int k0) {
        unsigned sb = smem_u32 + (unsigned)stg * 32768u;
        size_t kb = (size_t)k0 * 2;
#pragma unroll
        for (int i = 0; i < 2; i++) {
            unsigned d = sb + dsw[i];
            CP16(d,          Ahc + aoff[i] + kb);
            CP16(d + 8192u,  Alc + aoff[i] + kb);
            CP16(d + 16384u, Bhc + boff[i] + kb);
            CP16(d + 24576u, Blc + boff[i] + kb);
        }
        CP_COMMIT();
    };

    float acc[4][4][4];
#pragma unroll
    for (int i = 0; i < 4; i++)
#pragma unroll
        for (int j = 0; j < 4; j++)
#pragma unroll
            for (int r = 0; r < 4; r++) acc[i][j][r] = 0.0f;

    const int lt = lane >> 3, lr = lane & 7;
    unsigned a_base[4], b_base[2];
#pragma unroll
    for (int mf = 0; mf < 4; mf++) {
        int m = wm + mf * 16 + (lt & 1) * 8 + lr;
        a_base[mf] = swz(m, (lt >> 1) * 16);
    }
#pragma unroll
    for (int np = 0; np < 2; np++) {
        int n = wn + np * 16 + (lt >> 1) * 8 + lr;
        b_base[np] = swz(n, (lt & 1) * 16);
    }

    const int nk = K / 32;
    issue_stage(0, 0);
    issue_stage(1, 32);

    int cur = 0, nxt = 2;
    for (int kt = 0; kt < nk; kt++) {
        if (kt + 2 < nk) { CP_WAIT1(); } else { CP_WAIT0(); }
        __syncthreads();
        if (kt + 2 < nk) issue_stage(nxt, (kt + 2) * 32);

        const unsigned st = smem_u32 + (unsigned)cur * 32768u;
        const unsigned sAh = st, sAl = st + 8192u, sBh = st + 16384u, sBl = st + 24576u;

#pragma unroll
        for (int kk = 0; kk < 2; kk++) {
            const unsigned kb = kk * 32;   // XOR advance (bit 5 within swizzle field)
            unsigned ah[4][4], al[4][4];
#pragma unroll
            for (int mf = 0; mf < 4; mf++) {
                ldsm4(ah[mf][0], ah[mf][1], ah[mf][2], ah[mf][3], sAh + (a_base[mf] ^ kb));
                ldsm4(al[mf][0], al[mf][1], al[mf][2], al[mf][3], sAl + (a_base[mf] ^ kb));
            }
            unsigned bhf[4][2], blf[4][2];
#pragma unroll
            for (int np = 0; np < 2; np++) {
                ldsm4(bhf[2 * np][0], bhf[2 * np][1], bhf[2 * np + 1][0], bhf[2 * np + 1][1],
                      sBh + (b_base[np] ^ kb));
                ldsm4(blf[2 * np][0], blf[2 * np][1], blf[2 * np + 1][0], blf[2 * np + 1][1],
                      sBl + (b_base[np] ^ kb));
            }
#pragma unroll
            for (int mf = 0; mf < 4; mf++)
#pragma unroll
                for (int nf = 0; nf < 4; nf++) {
                    mma_bf16(acc[mf][nf], ah[mf][0], ah[mf][1], ah[mf][2], ah[mf][3],
                             bhf[nf][0], bhf[nf][1]);
                    mma_bf16(acc[mf][nf], ah[mf][0], ah[mf][1], ah[mf][2], ah[mf][3],
                             blf[nf][0], blf[nf][1]);
                    mma_bf16(acc[mf][nf], al[mf][0], al[mf][1], al[mf][2], al[mf][3],
                             bhf[nf][0], bhf[nf][1]);
                }
        }
        cur = (cur + 1 == 3) ? 0 : cur + 1;
        nxt = (nxt + 1 == 3) ? 0 : nxt + 1;
    }

    const int g = lane >> 2, th = lane & 3;
#pragma unroll
    for (int mf = 0; mf < 4; mf++) {
#pragma unroll
        for (int nf = 0; nf < 4; nf++) {
            int row = bm + wm + mf * 16 + g;
            int col = bn + wn + nf * 8 + 2 * th;
            *(float2*)(C + (size_t)row * N + col) =
                make_float2(acc[mf][nf][0], acc[mf][nf][1]);
            *(float2*)(C + (size_t)(row + 8) * N + col) =
                make_float2(acc[mf][nf][2], acc[mf][nf][3]);
        }
    }
}

// ---------------------------------------------------------------------------
// Phase 1: per-chunk sums of Tk_p(xk)*v per (b,h,chunk,d), plus chunk totals
// of Rk_p = sum_{s,d} Tk_p (block reduce over 64 threads).
// ---------------------------------------------------------------------------
__global__ __launch_bounds__(64) void chunk_kernel()
{
    const int blk = blockIdx.x;                 // b*512 + h*32 + c
    const int c = blk & 31, h = (blk >> 5) & 15, b = blk >> 9;
    const int d = threadIdx.x;

    const float* base = g_qkv + ((size_t)(b * S_LEN + c * CHS)) * (3 * DMODEL)
                        + DMODEL + h * DH + d;
    float kv[5] = {0, 0, 0, 0, 0};
    float rk[5] = {0, 0, 0, 0, 0};
#pragma unroll 4
    for (int s = 0; s < CHS; s++) {
        float kval = base[(size_t)s * (3 * DMODEL)];
        float vval = base[(size_t)s * (3 * DMODEL) + DMODEL];
        float t[5];
        cheb5(clampx(kval * 0.125f), t);
#pragma unroll
        for (int p = 0; p < 5; p++) { kv[p] += t[p] * vval; rk[p] += t[p]; }
    }
    const int bh = b * H_NUM + h;
#pragma unroll
    for (int p = 0; p < 5; p++)
        g_ckv[(((size_t)bh * 5 + p) * NCH + c) * DH + d] = kv[p];

    // block-reduce rk over 64 threads (2 warps)
    __shared__ float wred[5][2];
    const int lane = d & 31, w = d >> 5;
#pragma unroll
    for (int p = 0; p < 5; p++) {
        float v = rk[p];
#pragma unroll
        for (int o = 16; o > 0; o >>= 1) v += __shfl_down_sync(0xffffffffu, v, o);
        if (lane == 0) wred[p][w] = v;
    }
    __syncthreads();
    if (d == 0) {
#pragma unroll
        for (int p = 0; p < 5; p++)
            g_crk[((size_t)bh * 5 + p) * NCH + c] = wred[p][0] + wred[p][1];
    }
}

// ---------------------------------------------------------------------------
// Phase 2: exclusive prefix over chunks, in place (kv and rk).
// ---------------------------------------------------------------------------
#define NKV (BATCH * H_NUM * 5 * DH)      // 10240
#define NRK (BATCH * H_NUM * 5)           // 160
__global__ void prefix_kernel()
{
    const int t = blockIdx.x * blockDim.x + threadIdx.x;
    if (t < NKV) {
        const int d = t & 63;
        const int bhp = t >> 6;
        const size_t base = (size_t)bhp * NCH * DH + d;
        float run = 0.0f;
        for (int c = 0; c < NCH; c++) {
            size_t idx = base + (size_t)c * DH;
            float tmp = g_ckv[idx];
            g_ckv[idx] = run;
            run += tmp;
        }
    } else if (t < NKV + NRK) {
        const int bhp = t - NKV;
        const size_t base = (size_t)bhp * NCH;
        float run = 0.0f;
        for (int c = 0; c < NCH; c++) {
            float tmp = g_crk[base + c];
            g_crk[base + c] = run;
            run += tmp;
        }
    }
}

// ---------------------------------------------------------------------------
// den: one block per (b,h,chunk); 32 threads, thread = s within chunk.
// Each thread reduces over d; warp scan for the within-chunk k prefix.
// ---------------------------------------------------------------------------
__global__ __launch_bounds__(32) void den_kernel(Betas bt)
{
    const int blk = blockIdx.x;
    const int c = blk & 31, h = (blk >> 5) & 15, b = blk >> 9;
    const int sl = threadIdx.x;                    // 0..31
    const int bh = b * H_NUM + h;
    const int s = c * CHS + sl;

    const float* row = g_qkv + ((size_t)(b * S_LEN + s)) * (3 * DMODEL) + h * DH;

    float Aq[5] = {0, 0, 0, 0, 0};
    float Rk[5] = {0, 0, 0, 0, 0};
#pragma unroll 4
    for (int d4 = 0; d4 < DH; d4 += 4) {
        float4 q4 = *(const float4*)(row + d4);
        float4 k4 = *(const float4*)(row + DMODEL + d4);
        const float qa[4] = {q4.x, q4.y, q4.z, q4.w};
        const float ka[4] = {k4.x, k4.y, k4.z, k4.w};
#pragma unroll
        for (int j = 0; j < 4; j++) {
            float tq[5], tk[5];
            cheb5(clampx(qa[j] * 0.125f), tq);
            cheb5(clampx(ka[j] * 0.125f), tk);
#pragma unroll
            for (int p = 0; p < 5; p++) { Aq[p] += tq[p]; Rk[p] += tk[p]; }
        }
    }

    // warp inclusive scan over 32 s
    float dsum = 0.0f;
#pragma unroll
    for (int p = 0; p < 5; p++) {
        float v = Rk[p];
#pragma unroll
        for (int o = 1; o < 32; o <<= 1) {
            float t = __shfl_up_sync(0xffffffffu, v, o);
            if (sl >= o) v += t;
        }
        float C = v + g_crk[((size_t)bh * 5 + p) * NCH + c];
        dsum += bt.b[p] * Aq[p] * C;
    }
    g_den[bh * S_LEN + s] = dsum;
}

// ---------------------------------------------------------------------------
// Phase 3: rescan chunk; fuse numerator + normalize; emit bf16 hi/lo for GEMM2.
// ---------------------------------------------------------------------------
__global__ __launch_bounds__(64) void final_kernel(Betas bt)
{
    const int blk = blockIdx.x;
    const int c = blk & 31, h = (blk >> 5) & 15, b = blk >> 9;
    const int d = threadIdx.x;
    const int bh = b * H_NUM + h;

    float kv[5];
#pragma unroll
    for (int p = 0; p < 5; p++)
        kv[p] = g_ckv[(((size_t)bh * 5 + p) * NCH + c) * DH + d];

    const float* base = g_qkv + ((size_t)(b * S_LEN + c * CHS)) * (3 * DMODEL) + h * DH + d;
    const float* denb = g_den + bh * S_LEN + c * CHS;
    const size_t obase = ((size_t)(b * S_LEN + c * CHS)) * DMODEL + h * DH + d;

#pragma unroll 4
    for (int s = 0; s < CHS; s++) {
        const float* r = base + (size_t)s * (3 * DMODEL);
        float qv = r[0];
        float kval = r[DMODEL];
        float vval = r[2 * DMODEL];

        float tk[5];
        cheb5(clampx(kval * 0.125f), tk);
#pragma unroll
        for (int p = 0; p < 5; p++) kv[p] += tk[p] * vval;

        float tq[5];
        cheb5(clampx(qv * 0.125f), tq);
        float num = 0.0f;
#pragma unroll
        for (int p = 0; p < 5; p++) num += bt.b[p] * tq[p] * kv[p];

        float res = num / (denb[s] + 1e-7f);
        __nv_bfloat16 hi = __float2bfloat16(res);
        size_t idx = obase + (size_t)s * DMODEL;
        g_ath[idx] = hi;
        g_atl[idx] = __float2bfloat16(res - __bfloat162float(hi));
    }
}

// ---------------------------------------------------------------------------
extern "C" void kernel_launch(void* const* d_in, const int* in_sizes, int n_in,
                              void* d_out, int out_size)
{
    const float* x     = (const float*)d_in[0];   // (2,1024,1024)
    const float* W_in  = (const float*)d_in[1];   // (3072,1024)
    const float* W_out = (const float*)d_in[2];   // (1024,1024)
    float* out = (float*)d_out;                   // (2,1024,1024)

    float* qkv;
    cudaGetSymbolAddress((void**)&qkv, g_qkv);
    __nv_bfloat16 *xh, *xl, *wih, *wil, *woh, *wol, *ath, *atl;
    cudaGetSymbolAddress((void**)&xh,  g_xh);
    cudaGetSymbolAddress((void**)&xl,  g_xl);
    cudaGetSymbolAddress((void**)&wih, g_wih);
    cudaGetSymbolAddress((void**)&wil, g_wil);
    cudaGetSymbolAddress((void**)&woh, g_woh);
    cudaGetSymbolAddress((void**)&wol, g_wol);
    cudaGetSymbolAddress((void**)&ath, g_ath);
    cudaGetSymbolAddress((void**)&atl, g_atl);

    // beta[p] = tail[p+1] / sum(tail[1..5])
    double alpha[6], tail[7];
    tail[6] = 0.0;
    for (int j = 5; j >= 0; j--) {
        alpha[j] = pow((double)(j + 1), -1.5);
        tail[j] = tail[j + 1] + alpha[j];
    }
    double bsum = tail[1] + tail[2] + tail[3] + tail[4] + tail[5];
    Betas bt;
    for (int p = 0; p < 5; p++) bt.b[p] = (float)(tail[p + 1] / bsum);

    const int M = BATCH * S_LEN;           // 2048
    const int nx = M * DMODEL;             // 2M
    const int nw1 = 3 * DMODEL * DMODEL;   // 3M
    const int nw2 = DMODEL * DMODEL;       // 1M

    static bool attr_set = false;
    if (!attr_set) {
        cudaFuncSetAttribute(gemm_split, cudaFuncAttributeMaxDynamicSharedMemorySize, 98304);
        attr_set = true;
    }

    split3<<<(nx + nw1 + nw2) / 4 / 256, 256>>>(x, xh, xl, nx,
                                                W_in, wih, wil, nw1,
                                                W_out, woh, wol, nw2);
    gemm_split<<<dim3(3 * DMODEL / 128, M / 128), 256, 98304>>>(
        xh, xl, wih, wil, qkv, M, 3 * DMODEL, DMODEL);
    chunk_kernel<<<BATCH * H_NUM * NCH, 64>>>();
    prefix_kernel<<<(NKV + NRK + 255) / 256, 256>>>();
    den_kernel<<<BATCH * H_NUM * NCH, 32>>>(bt);
    final_kernel<<<BATCH * H_NUM * NCH, 64>>>(bt);
    gemm_split<<<dim3(DMODEL / 128, M / 128), 256, 98304>>>(
        ath, atl, woh, wol, out, M, DMODEL, DMODEL);
}

// round 7
// speedup vs baseline: 3.5104x; 1.0007x over previous
#include <cuda_runtime.h>
#include <cuda_bf16.h>
#include <cstdint>
#include <cmath>

// Problem constants
#define S_LEN   1024
#define DMODEL  1024
#define H_NUM   16
#define DH      64
#define BATCH   2
#define NCH     32     // chunks along S
#define CHS     32     // chunk length (S_LEN / NCH)

// Scratch (static device globals; no allocation allowed)
__device__ float g_qkv[(size_t)BATCH * S_LEN * 3 * DMODEL];   // 25.2 MB
__device__ float g_den[BATCH * H_NUM * S_LEN];                // 128 KB
__device__ float g_ckv[BATCH * H_NUM * 5 * NCH * DH];         // kv chunk sums -> exclusive prefix
__device__ float g_crk[BATCH * H_NUM * 5 * NCH];              // rk chunk sums -> exclusive prefix

// bf16 hi/lo split operands
__device__ __nv_bfloat16 g_xh[(size_t)BATCH * S_LEN * DMODEL];
__device__ __nv_bfloat16 g_xl[(size_t)BATCH * S_LEN * DMODEL];
__device__ __nv_bfloat16 g_wih[(size_t)3 * DMODEL * DMODEL];
__device__ __nv_bfloat16 g_wil[(size_t)3 * DMODEL * DMODEL];
__device__ __nv_bfloat16 g_woh[(size_t)DMODEL * DMODEL];
__device__ __nv_bfloat16 g_wol[(size_t)DMODEL * DMODEL];
__device__ __nv_bfloat16 g_ath[(size_t)BATCH * S_LEN * DMODEL];
__device__ __nv_bfloat16 g_atl[(size_t)BATCH * S_LEN * DMODEL];

struct Betas { float b[5]; };

__device__ __forceinline__ float clampx(float x) {
    return fminf(fmaxf(x, -1.0f + 1e-6f), 1.0f - 1e-6f);
}

__device__ __forceinline__ void cheb5(float x, float t[5]) {
    float x2 = x + x;
    float t1 = x;
    float t2 = x2 * t1 - 1.0f;
    float t3 = x2 * t2 - t1;
    float t4 = x2 * t3 - t2;
    float t5 = x2 * t4 - t3;
    t[0] = t1; t[1] = t2; t[2] = t3; t[3] = t4; t[4] = t5;
}

__device__ __forceinline__ unsigned pack2(__nv_bfloat16 a, __nv_bfloat16 b) {
    __nv_bfloat162 t(a, b);
    return *reinterpret_cast<unsigned*>(&t);
}

__device__ __forceinline__ void ldsm4(unsigned& r0, unsigned& r1, unsigned& r2, unsigned& r3,
                                      unsigned addr) {
    asm volatile("ldmatrix.sync.aligned.m8n8.x4.shared.b16 {%0,%1,%2,%3}, [%4];"
                 : "=r"(r0), "=r"(r1), "=r"(r2), "=r"(r3) : "r"(addr));
}

__device__ __forceinline__ void mma_bf16(float c[4],
                                         unsigned a0, unsigned a1, unsigned a2, unsigned a3,
                                         unsigned b0, unsigned b1) {
    asm volatile(
        "mma.sync.aligned.m16n8k16.row.col.f32.bf16.bf16.f32 "
        "{%0,%1,%2,%3}, {%4,%5,%6,%7}, {%8,%9}, {%0,%1,%2,%3};"
        : "+f"(c[0]), "+f"(c[1]), "+f"(c[2]), "+f"(c[3])
        : "r"(a0), "r"(a1), "r"(a2), "r"(a3), "r"(b0), "r"(b1));
}

#define CP16(dst, src) \
    asm volatile("cp.async.cg.shared.global [%0], [%1], 16;" :: "r"(dst), "l"(src))
#define CP_COMMIT() asm volatile("cp.async.commit_group;")
#define CP_WAIT1()  asm volatile("cp.async.wait_group 1;")
#define CP_WAIT0()  asm volatile("cp.async.wait_group 0;")

// swizzled byte offset inside a 128x32 bf16 tile (64B rows).
__device__ __forceinline__ unsigned swz(int m, int cbyte) {
    return (unsigned)((m << 6) + (cbyte ^ (((m >> 1) & 3) << 4)));
}

// ---------------------------------------------------------------------------
// split3: f32 -> bf16 hi + bf16 lo residual, three tensors in one launch
// ---------------------------------------------------------------------------
__global__ __launch_bounds__(256) void split3(
    const float* __restrict__ a, __nv_bfloat16* __restrict__ ah, __nv_bfloat16* __restrict__ al, int na,
    const float* __restrict__ b, __nv_bfloat16* __restrict__ bh, __nv_bfloat16* __restrict__ bl, int nb,
    const float* __restrict__ c, __nv_bfloat16* __restrict__ ch, __nv_bfloat16* __restrict__ cl, int nc)
{
    int i = (blockIdx.x * blockDim.x + threadIdx.x) * 4;
    const float* src; __nv_bfloat16 *hi, *lo; int off;
    if (i < na)           { src = a; hi = ah; lo = al; off = i; }
    else if (i < na + nb) { src = b; hi = bh; lo = bl; off = i - na; }
    else if (i < na + nb + nc) { src = c; hi = ch; lo = cl; off = i - na - nb; }
    else return;

    float4 v = *(const float4*)(src + off);
    __nv_bfloat16 h0 = __float2bfloat16(v.x), h1 = __float2bfloat16(v.y);
    __nv_bfloat16 h2 = __float2bfloat16(v.z), h3 = __float2bfloat16(v.w);
    __nv_bfloat16 l0 = __float2bfloat16(v.x - __bfloat162float(h0));
    __nv_bfloat16 l1 = __float2bfloat16(v.y - __bfloat162float(h1));
    __nv_bfloat16 l2 = __float2bfloat16(v.z - __bfloat162float(h2));
    __nv_bfloat16 l3 = __float2bfloat16(v.w - __bfloat162float(h3));
    *(uint2*)(hi + off) = make_uint2(pack2(h0, h1), pack2(h2, h3));
    *(uint2*)(lo + off) = make_uint2(pack2(l0, l1), pack2(l2, l3));
}

// ---------------------------------------------------------------------------
// bf16x3 GEMM, pre-split operands, 3-stage cp.async pipeline (1 sync/tile):
//   C[M,N] = (Ah+Al)[M,K] @ (Bh+Bl)[N,K]^T  (drop Al*Bl)
// BM=BN=128, BK=32, 256 threads (8 warps 2x4), warp tile 64x32.
// Dynamic smem: 3 stages x 32KB. launch_bounds(256,2) caps regs at 128 so
// two CTAs co-reside per SM (smem 2x96KB fits in 228KB).
// ---------------------------------------------------------------------------
__global__ __launch_bounds__(256, 2) void gemm_split(
    const __nv_bfloat16* __restrict__ Ahg, const __nv_bfloat16* __restrict__ Alg,
    const __nv_bfloat16* __restrict__ Bhg, const __nv_bfloat16* __restrict__ Blg,
    float* __restrict__ C, int M, int N, int K)
{
    extern __shared__ char dsmem[];
    const unsigned smem_u32 = (unsigned)__cvta_generic_to_shared(dsmem);

    const int tid  = threadIdx.x;
    const int wid  = tid >> 5;
    const int lane = tid & 31;
    const int wm = (wid >> 2) * 64;
    const int wn = (wid & 3) * 32;

    const int bm = blockIdx.y * 128;
    const int bn = blockIdx.x * 128;

    // copy mapping: chunk c = tid + i*256 (512 chunks of 16B per buffer)
    int crow[2], ccb[2];
    size_t aoff[2], boff[2];
    unsigned dsw[2];
#pragma unroll
    for (int i = 0; i < 2; i++) {
        int c = tid + i * 256;
        crow[i] = c >> 2;
        ccb[i]  = (c & 3) * 16;
        aoff[i] = (size_t)(bm + crow[i]) * K * 2 + ccb[i];
        boff[i] = (size_t)(bn + crow[i]) * K * 2 + ccb[i];
        dsw[i]  = swz(crow[i], ccb[i]);
    }
    const char* Ahc = (const char*)Ahg;
    const char* Alc = (const char*)Alg;
    const char* Bhc = (const char*)Bhg;
    const char* Blc = (const char*)Blg;

    auto issue_stage = [&](int stg, int k0) {
        unsigned sb = smem_u32 + (unsigned)stg * 32768u;
        size_t kb = (size_t)k0 * 2;
#pragma unroll
        for (int i = 0; i < 2; i++) {
            unsigned d = sb + dsw[i];
            CP16(d,          Ahc + aoff[i] + kb);
            CP16(d + 8192u,  Alc + aoff[i] + kb);
            CP16(d + 16384u, Bhc + boff[i] + kb);
            CP16(d + 24576u, Blc + boff[i] + kb);
        }
        CP_COMMIT();
    };

    float acc[4][4][4];
#pragma unroll
    for (int i = 0; i < 4; i++)
#pragma unroll
        for (int j = 0; j < 4; j++)
#pragma unroll
            for (int r = 0; r < 4; r++) acc[i][j][r] = 0.0f;

    const int lt = lane >> 3, lr = lane & 7;
    unsigned a_base[4], b_base[2];
#pragma unroll
    for (int mf = 0; mf < 4; mf++) {
        int m = wm + mf * 16 + (lt & 1) * 8 + lr;
        a_base[mf] = swz(m, (lt >> 1) * 16);
    }
#pragma unroll
    for (int np = 0; np < 2; np++) {
        int n = wn + np * 16 + (lt >> 1) * 8 + lr;
        b_base[np] = swz(n, (lt & 1) * 16);
    }

    const int nk = K / 32;
    issue_stage(0, 0);
    issue_stage(1, 32);

    int cur = 0, nxt = 2;
    for (int kt = 0; kt < nk; kt++) {
        if (kt + 2 < nk) { CP_WAIT1(); } else { CP_WAIT0(); }
        __syncthreads();
        if (kt + 2 < nk) issue_stage(nxt, (kt + 2) * 32);

        const unsigned st = smem_u32 + (unsigned)cur * 32768u;
        const unsigned sAh = st, sAl = st + 8192u, sBh = st + 16384u, sBl = st + 24576u;

#pragma unroll
        for (int kk = 0; kk < 2; kk++) {
            const unsigned kb = kk * 32;   // XOR advance (bit 5 within swizzle field)
            unsigned ah[4][4], al[4][4];
#pragma unroll
            for (int mf = 0; mf < 4; mf++) {
                ldsm4(ah[mf][0], ah[mf][1], ah[mf][2], ah[mf][3], sAh + (a_base[mf] ^ kb));
                ldsm4(al[mf][0], al[mf][1], al[mf][2], al[mf][3], sAl + (a_base[mf] ^ kb));
            }
            unsigned bhf[4][2], blf[4][2];
#pragma unroll
            for (int np = 0; np < 2; np++) {
                ldsm4(bhf[2 * np][0], bhf[2 * np][1], bhf[2 * np + 1][0], bhf[2 * np + 1][1],
                      sBh + (b_base[np] ^ kb));
                ldsm4(blf[2 * np][0], blf[2 * np][1], blf[2 * np + 1][0], blf[2 * np + 1][1],
                      sBl + (b_base[np] ^ kb));
            }
#pragma unroll
            for (int mf = 0; mf < 4; mf++)
#pragma unroll
                for (int nf = 0; nf < 4; nf++) {
                    mma_bf16(acc[mf][nf], ah[mf][0], ah[mf][1], ah[mf][2], ah[mf][3],
                             bhf[nf][0], bhf[nf][1]);
                    mma_bf16(acc[mf][nf], ah[mf][0], ah[mf][1], ah[mf][2], ah[mf][3],
                             blf[nf][0], blf[nf][1]);
                    mma_bf16(acc[mf][nf], al[mf][0], al[mf][1], al[mf][2], al[mf][3],
                             bhf[nf][0], bhf[nf][1]);
                }
        }
        cur = (cur + 1 == 3) ? 0 : cur + 1;
        nxt = (nxt + 1 == 3) ? 0 : nxt + 1;
    }

    const int g = lane >> 2, th = lane & 3;
#pragma unroll
    for (int mf = 0; mf < 4; mf++) {
#pragma unroll
        for (int nf = 0; nf < 4; nf++) {
            int row = bm + wm + mf * 16 + g;
            int col = bn + wn + nf * 8 + 2 * th;
            *(float2*)(C + (size_t)row * N + col) =
                make_float2(acc[mf][nf][0], acc[mf][nf][1]);
            *(float2*)(C + (size_t)(row + 8) * N + col) =
                make_float2(acc[mf][nf][2], acc[mf][nf][3]);
        }
    }
}

// ---------------------------------------------------------------------------
// Phase 1: per-chunk sums of Tk_p(xk)*v per (b,h,chunk,d), plus chunk totals
// of Rk_p = sum_{s,d} Tk_p (block reduce over 64 threads).
// ---------------------------------------------------------------------------
__global__ __launch_bounds__(64) void chunk_kernel()
{
    const int blk = blockIdx.x;                 // b*512 + h*32 + c
    const int c = blk & 31, h = (blk >> 5) & 15, b = blk >> 9;
    const int d = threadIdx.x;

    const float* base = g_qkv + ((size_t)(b * S_LEN + c * CHS)) * (3 * DMODEL)
                        + DMODEL + h * DH + d;
    float kv[5] = {0, 0, 0, 0, 0};
    float rk[5] = {0, 0, 0, 0, 0};
#pragma unroll 4
    for (int s = 0; s < CHS; s++) {
        float kval = base[(size_t)s * (3 * DMODEL)];
        float vval = base[(size_t)s * (3 * DMODEL) + DMODEL];
        float t[5];
        cheb5(clampx(kval * 0.125f), t);
#pragma unroll
        for (int p = 0; p < 5; p++) { kv[p] += t[p] * vval; rk[p] += t[p]; }
    }
    const int bh = b * H_NUM + h;
#pragma unroll
    for (int p = 0; p < 5; p++)
        g_ckv[(((size_t)bh * 5 + p) * NCH + c) * DH + d] = kv[p];

    // block-reduce rk over 64 threads (2 warps)
    __shared__ float wred[5][2];
    const int lane = d & 31, w = d >> 5;
#pragma unroll
    for (int p = 0; p < 5; p++) {
        float v = rk[p];
#pragma unroll
        for (int o = 16; o > 0; o >>= 1) v += __shfl_down_sync(0xffffffffu, v, o);
        if (lane == 0) wred[p][w] = v;
    }
    __syncthreads();
    if (d == 0) {
#pragma unroll
        for (int p = 0; p < 5; p++)
            g_crk[((size_t)bh * 5 + p) * NCH + c] = wred[p][0] + wred[p][1];
    }
}

// ---------------------------------------------------------------------------
// Phase 2: exclusive prefix over chunks, in place (kv and rk).
// Register-buffered: all NCH loads issued independently (MLP), then scanned.
// ---------------------------------------------------------------------------
#define NKV (BATCH * H_NUM * 5 * DH)      // 10240
#define NRK (BATCH * H_NUM * 5)           // 160
__global__ void prefix_kernel()
{
    const int t = blockIdx.x * blockDim.x + threadIdx.x;
    if (t < NKV) {
        const int d = t & 63;
        const int bhp = t >> 6;
        const size_t base = (size_t)bhp * NCH * DH + d;
        float vals[NCH];
#pragma unroll
        for (int c = 0; c < NCH; c++) vals[c] = g_ckv[base + (size_t)c * DH];
        float run = 0.0f;
#pragma unroll
        for (int c = 0; c < NCH; c++) {
            g_ckv[base + (size_t)c * DH] = run;
            run += vals[c];
        }
    } else if (t < NKV + NRK) {
        const int bhp = t - NKV;
        const size_t base = (size_t)bhp * NCH;
        float vals[NCH];
#pragma unroll
        for (int c = 0; c < NCH; c++) vals[c] = g_crk[base + c];
        float run = 0.0f;
#pragma unroll
        for (int c = 0; c < NCH; c++) {
            g_crk[base + c] = run;
            run += vals[c];
        }
    }
}

// ---------------------------------------------------------------------------
// den: one block per (b,h,chunk); 32 threads, thread = s within chunk.
// ---------------------------------------------------------------------------
__global__ __launch_bounds__(32) void den_kernel(Betas bt)
{
    const int blk = blockIdx.x;
    const int c = blk & 31, h = (blk >> 5) & 15, b = blk >> 9;
    const int sl = threadIdx.x;                    // 0..31
    const int bh = b * H_NUM + h;
    const int s = c * CHS + sl;

    const float* row = g_qkv + ((size_t)(b * S_LEN + s)) * (3 * DMODEL) + h * DH;

    float Aq[5] = {0, 0, 0, 0, 0};
    float Rk[5] = {0, 0, 0, 0, 0};
#pragma unroll 4
    for (int d4 = 0; d4 < DH; d4 += 4) {
        float4 q4 = *(const float4*)(row + d4);
        float4 k4 = *(const float4*)(row + DMODEL + d4);
        const float qa[4] = {q4.x, q4.y, q4.z, q4.w};
        const float ka[4] = {k4.x, k4.y, k4.z, k4.w};
#pragma unroll
        for (int j = 0; j < 4; j++) {
            float tq[5], tk[5];
            cheb5(clampx(qa[j] * 0.125f), tq);
            cheb5(clampx(ka[j] * 0.125f), tk);
#pragma unroll
            for (int p = 0; p < 5; p++) { Aq[p] += tq[p]; Rk[p] += tk[p]; }
        }
    }

    // warp inclusive scan over 32 s
    float dsum = 0.0f;
#pragma unroll
    for (int p = 0; p < 5; p++) {
        float v = Rk[p];
#pragma unroll
        for (int o = 1; o < 32; o <<= 1) {
            float t = __shfl_up_sync(0xffffffffu, v, o);
            if (sl >= o) v += t;
        }
        float C = v + g_crk[((size_t)bh * 5 + p) * NCH + c];
        dsum += bt.b[p] * Aq[p] * C;
    }
    g_den[bh * S_LEN + s] = dsum;
}

// ---------------------------------------------------------------------------
// Phase 3: rescan chunk; fuse numerator + normalize; emit bf16 hi/lo for GEMM2.
// ---------------------------------------------------------------------------
__global__ __launch_bounds__(64) void final_kernel(Betas bt)
{
    const int blk = blockIdx.x;
    const int c = blk & 31, h = (blk >> 5) & 15, b = blk >> 9;
    const int d = threadIdx.x;
    const int bh = b * H_NUM + h;

    float kv[5];
#pragma unroll
    for (int p = 0; p < 5; p++)
        kv[p] = g_ckv[(((size_t)bh * 5 + p) * NCH + c) * DH + d];

    const float* base = g_qkv + ((size_t)(b * S_LEN + c * CHS)) * (3 * DMODEL) + h * DH + d;
    const float* denb = g_den + bh * S_LEN + c * CHS;
    const size_t obase = ((size_t)(b * S_LEN + c * CHS)) * DMODEL + h * DH + d;

#pragma unroll 4
    for (int s = 0; s < CHS; s++) {
        const float* r = base + (size_t)s * (3 * DMODEL);
        float qv = r[0];
        float kval = r[DMODEL];
        float vval = r[2 * DMODEL];

        float tk[5];
        cheb5(clampx(kval * 0.125f), tk);
#pragma unroll
        for (int p = 0; p < 5; p++) kv[p] += tk[p] * vval;

        float tq[5];
        cheb5(clampx(qv * 0.125f), tq);
        float num = 0.0f;
#pragma unroll
        for (int p = 0; p < 5; p++) num += bt.b[p] * tq[p] * kv[p];

        float res = num / (denb[s] + 1e-7f);
        __nv_bfloat16 hi = __float2bfloat16(res);
        size_t idx = obase + (size_t)s * DMODEL;
        g_ath[idx] = hi;
        g_atl[idx] = __float2bfloat16(res - __bfloat162float(hi));
    }
}

// ---------------------------------------------------------------------------
extern "C" void kernel_launch(void* const* d_in, const int* in_sizes, int n_in,
                              void* d_out, int out_size)
{
    const float* x     = (const float*)d_in[0];   // (2,1024,1024)
    const float* W_in  = (const float*)d_in[1];   // (3072,1024)
    const float* W_out = (const float*)d_in[2];   // (1024,1024)
    float* out = (float*)d_out;                   // (2,1024,1024)

    float* qkv;
    cudaGetSymbolAddress((void**)&qkv, g_qkv);
    __nv_bfloat16 *xh, *xl, *wih, *wil, *woh, *wol, *ath, *atl;
    cudaGetSymbolAddress((void**)&xh,  g_xh);
    cudaGetSymbolAddress((void**)&xl,  g_xl);
    cudaGetSymbolAddress((void**)&wih, g_wih);
    cudaGetSymbolAddress((void**)&wil, g_wil);
    cudaGetSymbolAddress((void**)&woh, g_woh);
    cudaGetSymbolAddress((void**)&wol, g_wol);
    cudaGetSymbolAddress((void**)&ath, g_ath);
    cudaGetSymbolAddress((void**)&atl, g_atl);

    // beta[p] = tail[p+1] / sum(tail[1..5])
    double alpha[6], tail[7];
    tail[6] = 0.0;
    for (int j = 5; j >= 0; j--) {
        alpha[j] = pow((double)(j + 1), -1.5);
        tail[j] = tail[j + 1] + alpha[j];
    }
    double bsum = tail[1] + tail[2] + tail[3] + tail[4] + tail[5];
    Betas bt;
    for (int p = 0; p < 5; p++) bt.b[p] = (float)(tail[p + 1] / bsum);

    const int M = BATCH * S_LEN;           // 2048
    const int nx = M * DMODEL;             // 2M
    const int nw1 = 3 * DMODEL * DMODEL;   // 3M
    const int nw2 = DMODEL * DMODEL;       // 1M

    static bool attr_set = false;
    if (!attr_set) {
        cudaFuncSetAttribute(gemm_split, cudaFuncAttributeMaxDynamicSharedMemorySize, 98304);
        attr_set = true;
    }

    split3<<<(nx + nw1 + nw2) / 4 / 256, 256>>>(x, xh, xl, nx,
                                                W_in, wih, wil, nw1,
                                                W_out, woh, wol, nw2);
    gemm_split<<<dim3(3 * DMODEL / 128, M / 128), 256, 98304>>>(
        xh, xl, wih, wil, qkv, M, 3 * DMODEL, DMODEL);
    chunk_kernel<<<BATCH * H_NUM * NCH, 64>>>();
    prefix_kernel<<<(NKV + NRK + 255) / 256, 256>>>();
    den_kernel<<<BATCH * H_NUM * NCH, 32>>>(bt);
    final_kernel<<<BATCH * H_NUM * NCH, 64>>>(bt);
    gemm_split<<<dim3(DMODEL / 128, M / 128), 256, 98304>>>(
        ath, atl, woh, wol, out, M, DMODEL, DMODEL);
}

// round 10
// speedup vs baseline: 3.5475x; 1.0106x over previous
#include <cuda_runtime.h>
#include <cuda_bf16.h>
#include <cstdint>
#include <cmath>

// Problem constants
#define S_LEN   1024
#define DMODEL  1024
#define H_NUM   16
#define DH      64
#define BATCH   2
#define NCH     32     // chunks along S
#define CHS     32     // chunk length (S_LEN / NCH)

// Scratch (static device globals; no allocation allowed)
__device__ float g_qkv[(size_t)BATCH * S_LEN * 3 * DMODEL];   // 25.2 MB
__device__ float g_den[BATCH * H_NUM * S_LEN];                // 128 KB
__device__ float g_ckv[BATCH * H_NUM * 5 * NCH * DH];         // kv chunk sums -> exclusive prefix
__device__ float g_crk[BATCH * H_NUM * 5 * NCH];              // rk chunk sums -> exclusive prefix

// bf16 hi/lo split operands
__device__ __nv_bfloat16 g_xh[(size_t)BATCH * S_LEN * DMODEL];
__device__ __nv_bfloat16 g_xl[(size_t)BATCH * S_LEN * DMODEL];
__device__ __nv_bfloat16 g_wih[(size_t)3 * DMODEL * DMODEL];
__device__ __nv_bfloat16 g_wil[(size_t)3 * DMODEL * DMODEL];
__device__ __nv_bfloat16 g_woh[(size_t)DMODEL * DMODEL];
__device__ __nv_bfloat16 g_wol[(size_t)DMODEL * DMODEL];
__device__ __nv_bfloat16 g_ath[(size_t)BATCH * S_LEN * DMODEL];
__device__ __nv_bfloat16 g_atl[(size_t)BATCH * S_LEN * DMODEL];

struct Betas { float b[5]; };

__device__ __forceinline__ float clampx(float x) {
    return fminf(fmaxf(x, -1.0f + 1e-6f), 1.0f - 1e-6f);
}

__device__ __forceinline__ void cheb5(float x, float t[5]) {
    float x2 = x + x;
    float t1 = x;
    float t2 = x2 * t1 - 1.0f;
    float t3 = x2 * t2 - t1;
    float t4 = x2 * t3 - t2;
    float t5 = x2 * t4 - t3;
    t[0] = t1; t[1] = t2; t[2] = t3; t[3] = t4; t[4] = t5;
}

__device__ __forceinline__ unsigned pack2(__nv_bfloat16 a, __nv_bfloat16 b) {
    __nv_bfloat162 t(a, b);
    return *reinterpret_cast<unsigned*>(&t);
}

__device__ __forceinline__ void ldsm4(unsigned& r0, unsigned& r1, unsigned& r2, unsigned& r3,
                                      unsigned addr) {
    asm volatile("ldmatrix.sync.aligned.m8n8.x4.shared.b16 {%0,%1,%2,%3}, [%4];"
                 : "=r"(r0), "=r"(r1), "=r"(r2), "=r"(r3) : "r"(addr));
}

__device__ __forceinline__ void mma_bf16(float c[4],
                                         unsigned a0, unsigned a1, unsigned a2, unsigned a3,
                                         unsigned b0, unsigned b1) {
    asm volatile(
        "mma.sync.aligned.m16n8k16.row.col.f32.bf16.bf16.f32 "
        "{%0,%1,%2,%3}, {%4,%5,%6,%7}, {%8,%9}, {%0,%1,%2,%3};"
        : "+f"(c[0]), "+f"(c[1]), "+f"(c[2]), "+f"(c[3])
        : "r"(a0), "r"(a1), "r"(a2), "r"(a3), "r"(b0), "r"(b1));
}

#define CP16(dst, src) \
    asm volatile("cp.async.cg.shared.global [%0], [%1], 16;" :: "r"(dst), "l"(src))
#define CP_COMMIT() asm volatile("cp.async.commit_group;")
#define CP_WAIT1()  asm volatile("cp.async.wait_group 1;")
#define CP_WAIT0()  asm volatile("cp.async.wait_group 0;")

// swizzled byte offset inside a 128x32 bf16 tile (64B rows).
__device__ __forceinline__ unsigned swz(int m, int cbyte) {
    return (unsigned)((m << 6) + (cbyte ^ (((m >> 1) & 3) << 4)));
}

// ---------------------------------------------------------------------------
// split3: f32 -> bf16 hi + bf16 lo residual, three tensors in one launch
// ---------------------------------------------------------------------------
__global__ __launch_bounds__(256) void split3(
    const float* __restrict__ a, __nv_bfloat16* __restrict__ ah, __nv_bfloat16* __restrict__ al, int na,
    const float* __restrict__ b, __nv_bfloat16* __restrict__ bh, __nv_bfloat16* __restrict__ bl, int nb,
    const float* __restrict__ c, __nv_bfloat16* __restrict__ ch, __nv_bfloat16* __restrict__ cl, int nc)
{
    int i = (blockIdx.x * blockDim.x + threadIdx.x) * 4;
    const float* src; __nv_bfloat16 *hi, *lo; int off;
    if (i < na)           { src = a; hi = ah; lo = al; off = i; }
    else if (i < na + nb) { src = b; hi = bh; lo = bl; off = i - na; }
    else if (i < na + nb + nc) { src = c; hi = ch; lo = cl; off = i - na - nb; }
    else return;

    float4 v = *(const float4*)(src + off);
    __nv_bfloat16 h0 = __float2bfloat16(v.x), h1 = __float2bfloat16(v.y);
    __nv_bfloat16 h2 = __float2bfloat16(v.z), h3 = __float2bfloat16(v.w);
    __nv_bfloat16 l0 = __float2bfloat16(v.x - __bfloat162float(h0));
    __nv_bfloat16 l1 = __float2bfloat16(v.y - __bfloat162float(h1));
    __nv_bfloat16 l2 = __float2bfloat16(v.z - __bfloat162float(h2));
    __nv_bfloat16 l3 = __float2bfloat16(v.w - __bfloat162float(h3));
    *(uint2*)(hi + off) = make_uint2(pack2(h0, h1), pack2(h2, h3));
    *(uint2*)(lo + off) = make_uint2(pack2(l0, l1), pack2(l2, l3));
}

// ---------------------------------------------------------------------------
// bf16x3 GEMM, pre-split operands, 3-stage cp.async pipeline (1 sync/tile):
//   C[M,N] = (Ah+Al)[M,K] @ (Bh+Bl)[N,K]^T  (drop Al*Bl)
// BM=BN=128, BK=32, 256 threads (8 warps 2x4), warp tile 64x32.
// ---------------------------------------------------------------------------
__global__ __launch_bounds__(256) void gemm_split(
    const __nv_bfloat16* __restrict__ Ahg, const __nv_bfloat16* __restrict__ Alg,
    const __nv_bfloat16* __restrict__ Bhg, const __nv_bfloat16* __restrict__ Blg,
    float* __restrict__ C, int M, int N, int K)
{
    extern __shared__ char dsmem[];
    const unsigned smem_u32 = (unsigned)__cvta_generic_to_shared(dsmem);

    const int tid  = threadIdx.x;
    const int wid  = tid >> 5;
    const int lane = tid & 31;
    const int wm = (wid >> 2) * 64;
    const int wn = (wid & 3) * 32;

    const int bm = blockIdx.y * 128;
    const int bn = blockIdx.x * 128;

    int crow[2], ccb[2];
    size_t aoff[2], boff[2];
    unsigned dsw[2];
#pragma unroll
    for (int i = 0; i < 2; i++) {
        int c = tid + i * 256;
        crow[i] = c >> 2;
        ccb[i]  = (c & 3) * 16;
        aoff[i] = (size_t)(bm + crow[i]) * K * 2 + ccb[i];
        boff[i] = (size_t)(bn + crow[i]) * K * 2 + ccb[i];
        dsw[i]  = swz(crow[i], ccb[i]);
    }
    const char* Ahc = (const char*)Ahg;
    const char* Alc = (const char*)Alg;
    const char* Bhc = (const char*)Bhg;
    const char* Blc = (const char*)Blg;

    auto issue_stage = [&](int stg, int k0) {
        unsigned sb = smem_u32 + (unsigned)stg * 32768u;
        size_t kb = (size_t)k0 * 2;
#pragma unroll
        for (int i = 0; i < 2; i++) {
            unsigned d = sb + dsw[i];
            CP16(d,          Ahc + aoff[i] + kb);
            CP16(d + 8192u,  Alc + aoff[i] + kb);
            CP16(d + 16384u, Bhc + boff[i] + kb);
            CP16(d + 24576u, Blc + boff[i] + kb);
        }
        CP_COMMIT();
    };

    float acc[4][4][4];
#pragma unroll
    for (int i = 0; i < 4; i++)
#pragma unroll
        for (int j = 0; j < 4; j++)
#pragma unroll
            for (int r = 0; r < 4; r++) acc[i][j][r] = 0.0f;

    const int lt = lane >> 3, lr = lane & 7;
    unsigned a_base[4], b_base[2];
#pragma unroll
    for (int mf = 0; mf < 4; mf++) {
        int m = wm + mf * 16 + (lt & 1) * 8 + lr;
        a_base[mf] = swz(m, (lt >> 1) * 16);
    }
#pragma unroll
    for (int np = 0; np < 2; np++) {
        int n = wn + np * 16 + (lt >> 1) * 8 + lr;
        b_base[np] = swz(n, (lt & 1) * 16);
    }

    const int nk = K / 32;
    issue_stage(0, 0);
    issue_stage(1, 32);

    int cur = 0, nxt = 2;
    for (int kt = 0; kt < nk; kt++) {
        if (kt + 2 < nk) { CP_WAIT1(); } else { CP_WAIT0(); }
        __syncthreads();
        if (kt + 2 < nk) issue_stage(nxt, (kt + 2) * 32);

        const unsigned st = smem_u32 + (unsigned)cur * 32768u;
        const unsigned sAh = st, sAl = st + 8192u, sBh = st + 16384u, sBl = st + 24576u;

#pragma unroll
        for (int kk = 0; kk < 2; kk++) {
            const unsigned kb = kk * 32;   // XOR advance (bit 5 within swizzle field)
            unsigned ah[4][4], al[4][4];
#pragma unroll
            for (int mf = 0; mf < 4; mf++) {
                ldsm4(ah[mf][0], ah[mf][1], ah[mf][2], ah[mf][3], sAh + (a_base[mf] ^ kb));
                ldsm4(al[mf][0], al[mf][1], al[mf][2], al[mf][3], sAl + (a_base[mf] ^ kb));
            }
            unsigned bhf[4][2], blf[4][2];
#pragma unroll
            for (int np = 0; np < 2; np++) {
                ldsm4(bhf[2 * np][0], bhf[2 * np][1], bhf[2 * np + 1][0], bhf[2 * np + 1][1],
                      sBh + (b_base[np] ^ kb));
                ldsm4(blf[2 * np][0], blf[2 * np][1], blf[2 * np + 1][0], blf[2 * np + 1][1],
                      sBl + (b_base[np] ^ kb));
            }
#pragma unroll
            for (int mf = 0; mf < 4; mf++)
#pragma unroll
                for (int nf = 0; nf < 4; nf++) {
                    mma_bf16(acc[mf][nf], ah[mf][0], ah[mf][1], ah[mf][2], ah[mf][3],
                             bhf[nf][0], bhf[nf][1]);
                    mma_bf16(acc[mf][nf], ah[mf][0], ah[mf][1], ah[mf][2], ah[mf][3],
                             blf[nf][0], blf[nf][1]);
                    mma_bf16(acc[mf][nf], al[mf][0], al[mf][1], al[mf][2], al[mf][3],
                             bhf[nf][0], bhf[nf][1]);
                }
        }
        cur = (cur + 1 == 3) ? 0 : cur + 1;
        nxt = (nxt + 1 == 3) ? 0 : nxt + 1;
    }

    const int g = lane >> 2, th = lane & 3;
#pragma unroll
    for (int mf = 0; mf < 4; mf++) {
#pragma unroll
        for (int nf = 0; nf < 4; nf++) {
            int row = bm + wm + mf * 16 + g;
            int col = bn + wn + nf * 8 + 2 * th;
            *(float2*)(C + (size_t)row * N + col) =
                make_float2(acc[mf][nf][0], acc[mf][nf][1]);
            *(float2*)(C + (size_t)(row + 8) * N + col) =
                make_float2(acc[mf][nf][2], acc[mf][nf][3]);
        }
    }
}

// ---------------------------------------------------------------------------
// Phase 1: per-chunk sums of Tk_p(xk)*v per (b,h,chunk,d), plus chunk totals
// ---------------------------------------------------------------------------
__global__ __launch_bounds__(64) void chunk_kernel()
{
    const int blk = blockIdx.x;                 // b*512 + h*32 + c
    const int c = blk & 31, h = (blk >> 5) & 15, b = blk >> 9;
    const int d = threadIdx.x;

    const float* base = g_qkv + ((size_t)(b * S_LEN + c * CHS)) * (3 * DMODEL)
                        + DMODEL + h * DH + d;
    float kv[5] = {0, 0, 0, 0, 0};
    float rk[5] = {0, 0, 0, 0, 0};
#pragma unroll 4
    for (int s = 0; s < CHS; s++) {
        float kval = base[(size_t)s * (3 * DMODEL)];
        float vval = base[(size_t)s * (3 * DMODEL) + DMODEL];
        float t[5];
        cheb5(clampx(kval * 0.125f), t);
#pragma unroll
        for (int p = 0; p < 5; p++) { kv[p] += t[p] * vval; rk[p] += t[p]; }
    }
    const int bh = b * H_NUM + h;
#pragma unroll
    for (int p = 0; p < 5; p++)
        g_ckv[(((size_t)bh * 5 + p) * NCH + c) * DH + d] = kv[p];

    __shared__ float wred[5][2];
    const int lane = d & 31, w = d >> 5;
#pragma unroll
    for (int p = 0; p < 5; p++) {
        float v = rk[p];
#pragma unroll
        for (int o = 16; o > 0; o >>= 1) v += __shfl_down_sync(0xffffffffu, v, o);
        if (lane == 0) wred[p][w] = v;
    }
    __syncthreads();
    if (d == 0) {
#pragma unroll
        for (int p = 0; p < 5; p++)
            g_crk[((size_t)bh * 5 + p) * NCH + c] = wred[p][0] + wred[p][1];
    }
}

// ---------------------------------------------------------------------------
// Phase 2: block-parallel exclusive prefix over chunks.
// One block per bhp (=bh*5+p): 160 blocks x 1024 threads.
// Hillis-Steele scan over c in smem; warp 0 scans the rk row.
// ---------------------------------------------------------------------------
__global__ __launch_bounds__(1024) void prefix_kernel()
{
    const int bhp = blockIdx.x;          // 0..159
    const int tid = threadIdx.x;
    const int c  = tid >> 5;             // 0..31
    const int d0 = tid & 31;             // handles d0 and d0+32

    __shared__ float sm[2][NCH * DH];    // 2 x 8KB double buffer

    const size_t base = (size_t)bhp * NCH * DH;
    sm[0][c * DH + d0]      = g_ckv[base + c * DH + d0];
    sm[0][c * DH + d0 + 32] = g_ckv[base + c * DH + d0 + 32];
    __syncthreads();

    int src = 0;
#pragma unroll
    for (int st = 1; st < NCH; st <<= 1) {
        const int dst = src ^ 1;
        float v0 = sm[src][c * DH + d0];
        float v1 = sm[src][c * DH + d0 + 32];
        if (c >= st) {
            v0 += sm[src][(c - st) * DH + d0];
            v1 += sm[src][(c - st) * DH + d0 + 32];
        }
        sm[dst][c * DH + d0]      = v0;
        sm[dst][c * DH + d0 + 32] = v1;
        __syncthreads();
        src = dst;
    }

    // exclusive prefix out
    float e0 = (c == 0) ? 0.0f : sm[src][(c - 1) * DH + d0];
    float e1 = (c == 0) ? 0.0f : sm[src][(c - 1) * DH + d0 + 32];
    g_ckv[base + c * DH + d0]      = e0;
    g_ckv[base + c * DH + d0 + 32] = e1;

    // rk exclusive scan (warp 0)
    if (tid < 32) {
        const size_t rb = (size_t)bhp * NCH;
        float v = g_crk[rb + tid];
        float inc = v;
#pragma unroll
        for (int o = 1; o < 32; o <<= 1) {
            float t = __shfl_up_sync(0xffffffffu, inc, o);
            if (tid >= o) inc += t;
        }
        g_crk[rb + tid] = inc - v;
    }
}

// ---------------------------------------------------------------------------
// den: one block per (b,h,chunk); 64 threads = 2 warps splitting the d-range.
// warp w reduces d in [w*32, w*32+32); smem combine; warp 0 scans + writes.
// ---------------------------------------------------------------------------
__global__ __launch_bounds__(64) void den_kernel(Betas bt)
{
    const int blk = blockIdx.x;
    const int c = blk & 31, h = (blk >> 5) & 15, b = blk >> 9;
    const int sl = threadIdx.x & 31;               // s within chunk
    const int w  = threadIdx.x >> 5;               // d-half
    const int bh = b * H_NUM + h;
    const int s = c * CHS + sl;

    const float* row = g_qkv + ((size_t)(b * S_LEN + s)) * (3 * DMODEL) + h * DH + w * 32;

    float Aq[5] = {0, 0, 0, 0, 0};
    float Rk[5] = {0, 0, 0, 0, 0};
#pragma unroll
    for (int d4 = 0; d4 < 32; d4 += 4) {
        float4 q4 = *(const float4*)(row + d4);
        float4 k4 = *(const float4*)(row + DMODEL + d4);
        const float qa[4] = {q4.x, q4.y, q4.z, q4.w};
        const float ka[4] = {k4.x, k4.y, k4.z, k4.w};
#pragma unroll
        for (int j = 0; j < 4; j++) {
            float tq[5], tk[5];
            cheb5(clampx(qa[j] * 0.125f), tq);
            cheb5(clampx(ka[j] * 0.125f), tk);
#pragma unroll
            for (int p = 0; p < 5; p++) { Aq[p] += tq[p]; Rk[p] += tk[p]; }
        }
    }

    __shared__ float part[10][32];
    if (w == 1) {
#pragma unroll
        for (int p = 0; p < 5; p++) { part[p][sl] = Aq[p]; part[5 + p][sl] = Rk[p]; }
    }
    __syncthreads();
    if (w == 0) {
#pragma unroll
        for (int p = 0; p < 5; p++) { Aq[p] += part[p][sl]; Rk[p] += part[5 + p][sl]; }

        float dsum = 0.0f;
#pragma unroll
        for (int p = 0; p < 5; p++) {
            float v = Rk[p];
#pragma unroll
            for (int o = 1; o < 32; o <<= 1) {
                float t = __shfl_up_sync(0xffffffffu, v, o);
                if (sl >= o) v += t;
            }
            float C = v + g_crk[((size_t)bh * 5 + p) * NCH + c];
            dsum += bt.b[p] * Aq[p] * C;
        }
        g_den[bh * S_LEN + s] = dsum;
    }
}

// ---------------------------------------------------------------------------
// Phase 3: rescan chunk; fuse numerator + normalize; emit bf16 hi/lo for GEMM2.
// ---------------------------------------------------------------------------
__global__ __launch_bounds__(64) void final_kernel(Betas bt)
{
    const int blk = blockIdx.x;
    const int c = blk & 31, h = (blk >> 5) & 15, b = blk >> 9;
    const int d = threadIdx.x;
    const int bh = b * H_NUM + h;

    float kv[5];
#pragma unroll
    for (int p = 0; p < 5; p++)
        kv[p] = g_ckv[(((size_t)bh * 5 + p) * NCH + c) * DH + d];

    const float* base = g_qkv + ((size_t)(b * S_LEN + c * CHS)) * (3 * DMODEL) + h * DH + d;
    const float* denb = g_den + bh * S_LEN + c * CHS;
    const size_t obase = ((size_t)(b * S_LEN + c * CHS)) * DMODEL + h * DH + d;

#pragma unroll 4
    for (int s = 0; s < CHS; s++) {
        const float* r = base + (size_t)s * (3 * DMODEL);
        float qv = r[0];
        float kval = r[DMODEL];
        float vval = r[2 * DMODEL];

        float tk[5];
        cheb5(clampx(kval * 0.125f), tk);
#pragma unroll
        for (int p = 0; p < 5; p++) kv[p] += tk[p] * vval;

        float tq[5];
        cheb5(clampx(qv * 0.125f), tq);
        float num = 0.0f;
#pragma unroll
        for (int p = 0; p < 5; p++) num += bt.b[p] * tq[p] * kv[p];

        float res = num / (denb[s] + 1e-7f);
        __nv_bfloat16 hi = __float2bfloat16(res);
        size_t idx = obase + (size_t)s * DMODEL;
        g_ath[idx] = hi;
        g_atl[idx] = __float2bfloat16(res - __bfloat162float(hi));
    }
}

// ---------------------------------------------------------------------------
#define NKV (BATCH * H_NUM * 5 * DH)
#define NRK (BATCH * H_NUM * 5)

extern "C" void kernel_launch(void* const* d_in, const int* in_sizes, int n_in,
                              void* d_out, int out_size)
{
    const float* x     = (const float*)d_in[0];   // (2,1024,1024)
    const float* W_in  = (const float*)d_in[1];   // (3072,1024)
    const float* W_out = (const float*)d_in[2];   // (1024,1024)
    float* out = (float*)d_out;                   // (2,1024,1024)

    float* qkv;
    cudaGetSymbolAddress((void**)&qkv, g_qkv);
    __nv_bfloat16 *xh, *xl, *wih, *wil, *woh, *wol, *ath, *atl;
    cudaGetSymbolAddress((void**)&xh,  g_xh);
    cudaGetSymbolAddress((void**)&xl,  g_xl);
    cudaGetSymbolAddress((void**)&wih, g_wih);
    cudaGetSymbolAddress((void**)&wil, g_wil);
    cudaGetSymbolAddress((void**)&woh, g_woh);
    cudaGetSymbolAddress((void**)&wol, g_wol);
    cudaGetSymbolAddress((void**)&ath, g_ath);
    cudaGetSymbolAddress((void**)&atl, g_atl);

    // beta[p] = tail[p+1] / sum(tail[1..5])
    double alpha[6], tail[7];
    tail[6] = 0.0;
    for (int j = 5; j >= 0; j--) {
        alpha[j] = pow((double)(j + 1), -1.5);
        tail[j] = tail[j + 1] + alpha[j];
    }
    double bsum = tail[1] + tail[2] + tail[3] + tail[4] + tail[5];
    Betas bt;
    for (int p = 0; p < 5; p++) bt.b[p] = (float)(tail[p + 1] / bsum);

    const int M = BATCH * S_LEN;           // 2048
    const int nx = M * DMODEL;             // 2M
    const int nw1 = 3 * DMODEL * DMODEL;   // 3M
    const int nw2 = DMODEL * DMODEL;       // 1M

    static bool attr_set = false;
    if (!attr_set) {
        cudaFuncSetAttribute(gemm_split, cudaFuncAttributeMaxDynamicSharedMemorySize, 98304);
        attr_set = true;
    }

    split3<<<(nx + nw1 + nw2) / 4 / 256, 256>>>(x, xh, xl, nx,
                                                W_in, wih, wil, nw1,
                                                W_out, woh, wol, nw2);
    gemm_split<<<dim3(3 * DMODEL / 128, M / 128), 256, 98304>>>(
        xh, xl, wih, wil, qkv, M, 3 * DMODEL, DMODEL);
    chunk_kernel<<<BATCH * H_NUM * NCH, 64>>>();
    prefix_kernel<<<NRK, 1024>>>();
    den_kernel<<<BATCH * H_NUM * NCH, 64>>>(bt);
    final_kernel<<<BATCH * H_NUM * NCH, 64>>>(bt);
    gemm_split<<<dim3(DMODEL / 128, M / 128), 256, 98304>>>(
        ath, atl, woh, wol, out, M, DMODEL, DMODEL);
}

// round 11
// speedup vs baseline: 3.5555x; 1.0023x over previous
#include <cuda_runtime.h>
#include <cuda_bf16.h>
#include <cstdint>
#include <cmath>

// Problem constants
#define S_LEN   1024
#define DMODEL  1024
#define H_NUM   16
#define DH      64
#define BATCH   2
#define NCH     32     // chunks along S
#define CHS     32     // chunk length (S_LEN / NCH)

// Scratch (static device globals; no allocation allowed)
__device__ float g_qkv[(size_t)BATCH * S_LEN * 3 * DMODEL];   // 25.2 MB
__device__ float g_den[BATCH * H_NUM * S_LEN];                // 128 KB
__device__ float g_ckv[BATCH * H_NUM * 5 * NCH * DH];         // kv chunk sums -> exclusive prefix
__device__ float g_crk[BATCH * H_NUM * 5 * NCH];              // rk chunk sums -> exclusive prefix

// bf16 hi/lo split operands
__device__ __nv_bfloat16 g_xh[(size_t)BATCH * S_LEN * DMODEL];
__device__ __nv_bfloat16 g_xl[(size_t)BATCH * S_LEN * DMODEL];
__device__ __nv_bfloat16 g_wih[(size_t)3 * DMODEL * DMODEL];
__device__ __nv_bfloat16 g_wil[(size_t)3 * DMODEL * DMODEL];
__device__ __nv_bfloat16 g_woh[(size_t)DMODEL * DMODEL];
__device__ __nv_bfloat16 g_wol[(size_t)DMODEL * DMODEL];
__device__ __nv_bfloat16 g_ath[(size_t)BATCH * S_LEN * DMODEL];
__device__ __nv_bfloat16 g_atl[(size_t)BATCH * S_LEN * DMODEL];

struct Betas { float b[5]; };

__device__ __forceinline__ float clampx(float x) {
    return fminf(fmaxf(x, -1.0f + 1e-6f), 1.0f - 1e-6f);
}

__device__ __forceinline__ void cheb5(float x, float t[5]) {
    float x2 = x + x;
    float t1 = x;
    float t2 = x2 * t1 - 1.0f;
    float t3 = x2 * t2 - t1;
    float t4 = x2 * t3 - t2;
    float t5 = x2 * t4 - t3;
    t[0] = t1; t[1] = t2; t[2] = t3; t[3] = t4; t[4] = t5;
}

__device__ __forceinline__ unsigned pack2(__nv_bfloat16 a, __nv_bfloat16 b) {
    __nv_bfloat162 t(a, b);
    return *reinterpret_cast<unsigned*>(&t);
}

__device__ __forceinline__ void ldsm4(unsigned& r0, unsigned& r1, unsigned& r2, unsigned& r3,
                                      unsigned addr) {
    asm volatile("ldmatrix.sync.aligned.m8n8.x4.shared.b16 {%0,%1,%2,%3}, [%4];"
                 : "=r"(r0), "=r"(r1), "=r"(r2), "=r"(r3) : "r"(addr));
}

__device__ __forceinline__ void mma_bf16(float c[4],
                                         unsigned a0, unsigned a1, unsigned a2, unsigned a3,
                                         unsigned b0, unsigned b1) {
    asm volatile(
        "mma.sync.aligned.m16n8k16.row.col.f32.bf16.bf16.f32 "
        "{%0,%1,%2,%3}, {%4,%5,%6,%7}, {%8,%9}, {%0,%1,%2,%3};"
        : "+f"(c[0]), "+f"(c[1]), "+f"(c[2]), "+f"(c[3])
        : "r"(a0), "r"(a1), "r"(a2), "r"(a3), "r"(b0), "r"(b1));
}

#define CP16(dst, src) \
    asm volatile("cp.async.cg.shared.global [%0], [%1], 16;" :: "r"(dst), "l"(src))
#define CP_COMMIT() asm volatile("cp.async.commit_group;")
#define CP_WAIT1()  asm volatile("cp.async.wait_group 1;")
#define CP_WAIT0()  asm volatile("cp.async.wait_group 0;")

// swizzled byte offset inside a 128x32 bf16 tile (64B rows).
__device__ __forceinline__ unsigned swz(int m, int cbyte) {
    return (unsigned)((m << 6) + (cbyte ^ (((m >> 1) & 3) << 4)));
}

// ---------------------------------------------------------------------------
// split3: f32 -> bf16 hi + bf16 lo residual, three tensors in one launch
// ---------------------------------------------------------------------------
__global__ __launch_bounds__(256) void split3(
    const float* __restrict__ a, __nv_bfloat16* __restrict__ ah, __nv_bfloat16* __restrict__ al, int na,
    const float* __restrict__ b, __nv_bfloat16* __restrict__ bh, __nv_bfloat16* __restrict__ bl, int nb,
    const float* __restrict__ c, __nv_bfloat16* __restrict__ ch, __nv_bfloat16* __restrict__ cl, int nc)
{
    int i = (blockIdx.x * blockDim.x + threadIdx.x) * 4;
    const float* src; __nv_bfloat16 *hi, *lo; int off;
    if (i < na)           { src = a; hi = ah; lo = al; off = i; }
    else if (i < na + nb) { src = b; hi = bh; lo = bl; off = i - na; }
    else if (i < na + nb + nc) { src = c; hi = ch; lo = cl; off = i - na - nb; }
    else return;

    float4 v = *(const float4*)(src + off);
    __nv_bfloat16 h0 = __float2bfloat16(v.x), h1 = __float2bfloat16(v.y);
    __nv_bfloat16 h2 = __float2bfloat16(v.z), h3 = __float2bfloat16(v.w);
    __nv_bfloat16 l0 = __float2bfloat16(v.x - __bfloat162float(h0));
    __nv_bfloat16 l1 = __float2bfloat16(v.y - __bfloat162float(h1));
    __nv_bfloat16 l2 = __float2bfloat16(v.z - __bfloat162float(h2));
    __nv_bfloat16 l3 = __float2bfloat16(v.w - __bfloat162float(h3));
    *(uint2*)(hi + off) = make_uint2(pack2(h0, h1), pack2(h2, h3));
    *(uint2*)(lo + off) = make_uint2(pack2(l0, l1), pack2(l2, l3));
}

// ---------------------------------------------------------------------------
// bf16x3 GEMM, pre-split operands, 3-stage cp.async pipeline (1 sync/tile):
//   C[M,N] = (Ah+Al)[M,K] @ (Bh+Bl)[N,K]^T  (drop Al*Bl)
// BM=BN=128, BK=32, 256 threads (8 warps 2x4), warp tile 64x32.
// MMA issued in 3 passes (hh, hl, lh) so same-accumulator mmas are 16 apart
// (back-to-back same-acc mma serializes on HMMA latency).
// ---------------------------------------------------------------------------
__global__ __launch_bounds__(256) void gemm_split(
    const __nv_bfloat16* __restrict__ Ahg, const __nv_bfloat16* __restrict__ Alg,
    const __nv_bfloat16* __restrict__ Bhg, const __nv_bfloat16* __restrict__ Blg,
    float* __restrict__ C, int M, int N, int K)
{
    extern __shared__ char dsmem[];
    const unsigned smem_u32 = (unsigned)__cvta_generic_to_shared(dsmem);

    const int tid  = threadIdx.x;
    const int wid  = tid >> 5;
    const int lane = tid & 31;
    const int wm = (wid >> 2) * 64;
    const int wn = (wid & 3) * 32;

    const int bm = blockIdx.y * 128;
    const int bn = blockIdx.x * 128;

    int crow[2], ccb[2];
    size_t aoff[2], boff[2];
    unsigned dsw[2];
#pragma unroll
    for (int i = 0; i < 2; i++) {
        int c = tid + i * 256;
        crow[i] = c >> 2;
        ccb[i]  = (c & 3) * 16;
        aoff[i] = (size_t)(bm + crow[i]) * K * 2 + ccb[i];
        boff[i] = (size_t)(bn + crow[i]) * K * 2 + ccb[i];
        dsw[i]  = swz(crow[i], ccb[i]);
    }
    const char* Ahc = (const char*)Ahg;
    const char* Alc = (const char*)Alg;
    const char* Bhc = (const char*)Bhg;
    const char* Blc = (const char*)Blg;

    auto issue_stage = [&](int stg, int k0) {
        unsigned sb = smem_u32 + (unsigned)stg * 32768u;
        size_t kb = (size_t)k0 * 2;
#pragma unroll
        for (int i = 0; i < 2; i++) {
            unsigned d = sb + dsw[i];
            CP16(d,          Ahc + aoff[i] + kb);
            CP16(d + 8192u,  Alc + aoff[i] + kb);
            CP16(d + 16384u, Bhc + boff[i] + kb);
            CP16(d + 24576u, Blc + boff[i] + kb);
        }
        CP_COMMIT();
    };

    float acc[4][4][4];
#pragma unroll
    for (int i = 0; i < 4; i++)
#pragma unroll
        for (int j = 0; j < 4; j++)
#pragma unroll
            for (int r = 0; r < 4; r++) acc[i][j][r] = 0.0f;

    const int lt = lane >> 3, lr = lane & 7;
    unsigned a_base[4], b_base[2];
#pragma unroll
    for (int mf = 0; mf < 4; mf++) {
        int m = wm + mf * 16 + (lt & 1) * 8 + lr;
        a_base[mf] = swz(m, (lt >> 1) * 16);
    }
#pragma unroll
    for (int np = 0; np < 2; np++) {
        int n = wn + np * 16 + (lt >> 1) * 8 + lr;
        b_base[np] = swz(n, (lt & 1) * 16);
    }

    const int nk = K / 32;
    issue_stage(0, 0);
    issue_stage(1, 32);

    int cur = 0, nxt = 2;
    for (int kt = 0; kt < nk; kt++) {
        if (kt + 2 < nk) { CP_WAIT1(); } else { CP_WAIT0(); }
        __syncthreads();
        if (kt + 2 < nk) issue_stage(nxt, (kt + 2) * 32);

        const unsigned st = smem_u32 + (unsigned)cur * 32768u;
        const unsigned sAh = st, sAl = st + 8192u, sBh = st + 16384u, sBl = st + 24576u;

#pragma unroll
        for (int kk = 0; kk < 2; kk++) {
            const unsigned kb = kk * 32;   // XOR advance (bit 5 within swizzle field)
            unsigned ah[4][4], al[4][4];
#pragma unroll
            for (int mf = 0; mf < 4; mf++) {
                ldsm4(ah[mf][0], ah[mf][1], ah[mf][2], ah[mf][3], sAh + (a_base[mf] ^ kb));
                ldsm4(al[mf][0], al[mf][1], al[mf][2], al[mf][3], sAl + (a_base[mf] ^ kb));
            }
            unsigned bhf[4][2], blf[4][2];
#pragma unroll
            for (int np = 0; np < 2; np++) {
                ldsm4(bhf[2 * np][0], bhf[2 * np][1], bhf[2 * np + 1][0], bhf[2 * np + 1][1],
                      sBh + (b_base[np] ^ kb));
                ldsm4(blf[2 * np][0], blf[2 * np][1], blf[2 * np + 1][0], blf[2 * np + 1][1],
                      sBl + (b_base[np] ^ kb));
            }
            // Pass 1: hh
#pragma unroll
            for (int mf = 0; mf < 4; mf++)
#pragma unroll
                for (int nf = 0; nf < 4; nf++)
                    mma_bf16(acc[mf][nf], ah[mf][0], ah[mf][1], ah[mf][2], ah[mf][3],
                             bhf[nf][0], bhf[nf][1]);
            // Pass 2: hl
#pragma unroll
            for (int mf = 0; mf < 4; mf++)
#pragma unroll
                for (int nf = 0; nf < 4; nf++)
                    mma_bf16(acc[mf][nf], ah[mf][0], ah[mf][1], ah[mf][2], ah[mf][3],
                             blf[nf][0], blf[nf][1]);
            // Pass 3: lh
#pragma unroll
            for (int mf = 0; mf < 4; mf++)
#pragma unroll
                for (int nf = 0; nf < 4; nf++)
                    mma_bf16(acc[mf][nf], al[mf][0], al[mf][1], al[mf][2], al[mf][3],
                             bhf[nf][0], bhf[nf][1]);
        }
        cur = (cur + 1 == 3) ? 0 : cur + 1;
        nxt = (nxt + 1 == 3) ? 0 : nxt + 1;
    }

    const int g = lane >> 2, th = lane & 3;
#pragma unroll
    for (int mf = 0; mf < 4; mf++) {
#pragma unroll
        for (int nf = 0; nf < 4; nf++) {
            int row = bm + wm + mf * 16 + g;
            int col = bn + wn + nf * 8 + 2 * th;
            *(float2*)(C + (size_t)row * N + col) =
                make_float2(acc[mf][nf][0], acc[mf][nf][1]);
            *(float2*)(C + (size_t)(row + 8) * N + col) =
                make_float2(acc[mf][nf][2], acc[mf][nf][3]);
        }
    }
}

// ---------------------------------------------------------------------------
// Phase 1: per-chunk sums of Tk_p(xk)*v per (b,h,chunk,d), plus chunk totals
// ---------------------------------------------------------------------------
__global__ __launch_bounds__(64) void chunk_kernel()
{
    const int blk = blockIdx.x;                 // b*512 + h*32 + c
    const int c = blk & 31, h = (blk >> 5) & 15, b = blk >> 9;
    const int d = threadIdx.x;

    const float* base = g_qkv + ((size_t)(b * S_LEN + c * CHS)) * (3 * DMODEL)
                        + DMODEL + h * DH + d;
    float kv[5] = {0, 0, 0, 0, 0};
    float rk[5] = {0, 0, 0, 0, 0};
#pragma unroll 4
    for (int s = 0; s < CHS; s++) {
        float kval = base[(size_t)s * (3 * DMODEL)];
        float vval = base[(size_t)s * (3 * DMODEL) + DMODEL];
        float t[5];
        cheb5(clampx(kval * 0.125f), t);
#pragma unroll
        for (int p = 0; p < 5; p++) { kv[p] += t[p] * vval; rk[p] += t[p]; }
    }
    const int bh = b * H_NUM + h;
#pragma unroll
    for (int p = 0; p < 5; p++)
        g_ckv[(((size_t)bh * 5 + p) * NCH + c) * DH + d] = kv[p];

    __shared__ float wred[5][2];
    const int lane = d & 31, w = d >> 5;
#pragma unroll
    for (int p = 0; p < 5; p++) {
        float v = rk[p];
#pragma unroll
        for (int o = 16; o > 0; o >>= 1) v += __shfl_down_sync(0xffffffffu, v, o);
        if (lane == 0) wred[p][w] = v;
    }
    __syncthreads();
    if (d == 0) {
#pragma unroll
        for (int p = 0; p < 5; p++)
            g_crk[((size_t)bh * 5 + p) * NCH + c] = wred[p][0] + wred[p][1];
    }
}

// ---------------------------------------------------------------------------
// Phase 2: block-parallel exclusive prefix over chunks.
// One block per bhp (=bh*5+p): 160 blocks x 1024 threads.
// ---------------------------------------------------------------------------
__global__ __launch_bounds__(1024) void prefix_kernel()
{
    const int bhp = blockIdx.x;          // 0..159
    const int tid = threadIdx.x;
    const int c  = tid >> 5;             // 0..31
    const int d0 = tid & 31;             // handles d0 and d0+32

    __shared__ float sm[2][NCH * DH];    // 2 x 8KB double buffer

    const size_t base = (size_t)bhp * NCH * DH;
    sm[0][c * DH + d0]      = g_ckv[base + c * DH + d0];
    sm[0][c * DH + d0 + 32] = g_ckv[base + c * DH + d0 + 32];
    __syncthreads();

    int src = 0;
#pragma unroll
    for (int st = 1; st < NCH; st <<= 1) {
        const int dst = src ^ 1;
        float v0 = sm[src][c * DH + d0];
        float v1 = sm[src][c * DH + d0 + 32];
        if (c >= st) {
            v0 += sm[src][(c - st) * DH + d0];
            v1 += sm[src][(c - st) * DH + d0 + 32];
        }
        sm[dst][c * DH + d0]      = v0;
        sm[dst][c * DH + d0 + 32] = v1;
        __syncthreads();
        src = dst;
    }

    float e0 = (c == 0) ? 0.0f : sm[src][(c - 1) * DH + d0];
    float e1 = (c == 0) ? 0.0f : sm[src][(c - 1) * DH + d0 + 32];
    g_ckv[base + c * DH + d0]      = e0;
    g_ckv[base + c * DH + d0 + 32] = e1;

    if (tid < 32) {
        const size_t rb = (size_t)bhp * NCH;
        float v = g_crk[rb + tid];
        float inc = v;
#pragma unroll
        for (int o = 1; o < 32; o <<= 1) {
            float t = __shfl_up_sync(0xffffffffu, inc, o);
            if (tid >= o) inc += t;
        }
        g_crk[rb + tid] = inc - v;
    }
}

// ---------------------------------------------------------------------------
// den: one block per (b,h,chunk); 64 threads = 2 warps splitting the d-range.
// ---------------------------------------------------------------------------
__global__ __launch_bounds__(64) void den_kernel(Betas bt)
{
    const int blk = blockIdx.x;
    const int c = blk & 31, h = (blk >> 5) & 15, b = blk >> 9;
    const int sl = threadIdx.x & 31;               // s within chunk
    const int w  = threadIdx.x >> 5;               // d-half
    const int bh = b * H_NUM + h;
    const int s = c * CHS + sl;

    const float* row = g_qkv + ((size_t)(b * S_LEN + s)) * (3 * DMODEL) + h * DH + w * 32;

    float Aq[5] = {0, 0, 0, 0, 0};
    float Rk[5] = {0, 0, 0, 0, 0};
#pragma unroll
    for (int d4 = 0; d4 < 32; d4 += 4) {
        float4 q4 = *(const float4*)(row + d4);
        float4 k4 = *(const float4*)(row + DMODEL + d4);
        const float qa[4] = {q4.x, q4.y, q4.z, q4.w};
        const float ka[4] = {k4.x, k4.y, k4.z, k4.w};
#pragma unroll
        for (int j = 0; j < 4; j++) {
            float tq[5], tk[5];
            cheb5(clampx(qa[j] * 0.125f), tq);
            cheb5(clampx(ka[j] * 0.125f), tk);
#pragma unroll
            for (int p = 0; p < 5; p++) { Aq[p] += tq[p]; Rk[p] += tk[p]; }
        }
    }

    __shared__ float part[10][32];
    if (w == 1) {
#pragma unroll
        for (int p = 0; p < 5; p++) { part[p][sl] = Aq[p]; part[5 + p][sl] = Rk[p]; }
    }
    __syncthreads();
    if (w == 0) {
#pragma unroll
        for (int p = 0; p < 5; p++) { Aq[p] += part[p][sl]; Rk[p] += part[5 + p][sl]; }

        float dsum = 0.0f;
#pragma unroll
        for (int p = 0; p < 5; p++) {
            float v = Rk[p];
#pragma unroll
            for (int o = 1; o < 32; o <<= 1) {
                float t = __shfl_up_sync(0xffffffffu, v, o);
                if (sl >= o) v += t;
            }
            float C = v + g_crk[((size_t)bh * 5 + p) * NCH + c];
            dsum += bt.b[p] * Aq[p] * C;
        }
        g_den[bh * S_LEN + s] = dsum;
    }
}

// ---------------------------------------------------------------------------
// Phase 3: rescan chunk; fuse numerator + normalize; emit bf16 hi/lo for GEMM2.
// ---------------------------------------------------------------------------
__global__ __launch_bounds__(64) void final_kernel(Betas bt)
{
    const int blk = blockIdx.x;
    const int c = blk & 31, h = (blk >> 5) & 15, b = blk >> 9;
    const int d = threadIdx.x;
    const int bh = b * H_NUM + h;

    float kv[5];
#pragma unroll
    for (int p = 0; p < 5; p++)
        kv[p] = g_ckv[(((size_t)bh * 5 + p) * NCH + c) * DH + d];

    const float* base = g_qkv + ((size_t)(b * S_LEN + c * CHS)) * (3 * DMODEL) + h * DH + d;
    const float* denb = g_den + bh * S_LEN + c * CHS;
    const size_t obase = ((size_t)(b * S_LEN + c * CHS)) * DMODEL + h * DH + d;

#pragma unroll 4
    for (int s = 0; s < CHS; s++) {
        const float* r = base + (size_t)s * (3 * DMODEL);
        float qv = r[0];
        float kval = r[DMODEL];
        float vval = r[2 * DMODEL];

        float tk[5];
        cheb5(clampx(kval * 0.125f), tk);
#pragma unroll
        for (int p = 0; p < 5; p++) kv[p] += tk[p] * vval;

        float tq[5];
        cheb5(clampx(qv * 0.125f), tq);
        float num = 0.0f;
#pragma unroll
        for (int p = 0; p < 5; p++) num += bt.b[p] * tq[p] * kv[p];

        float res = num / (denb[s] + 1e-7f);
        __nv_bfloat16 hi = __float2bfloat16(res);
        size_t idx = obase + (size_t)s * DMODEL;
        g_ath[idx] = hi;
        g_atl[idx] = __float2bfloat16(res - __bfloat162float(hi));
    }
}

// ---------------------------------------------------------------------------
#define NKV (BATCH * H_NUM * 5 * DH)
#define NRK (BATCH * H_NUM * 5)

extern "C" void kernel_launch(void* const* d_in, const int* in_sizes, int n_in,
                              void* d_out, int out_size)
{
    const float* x     = (const float*)d_in[0];   // (2,1024,1024)
    const float* W_in  = (const float*)d_in[1];   // (3072,1024)
    const float* W_out = (const float*)d_in[2];   // (1024,1024)
    float* out = (float*)d_out;                   // (2,1024,1024)

    float* qkv;
    cudaGetSymbolAddress((void**)&qkv, g_qkv);
    __nv_bfloat16 *xh, *xl, *wih, *wil, *woh, *wol, *ath, *atl;
    cudaGetSymbolAddress((void**)&xh,  g_xh);
    cudaGetSymbolAddress((void**)&xl,  g_xl);
    cudaGetSymbolAddress((void**)&wih, g_wih);
    cudaGetSymbolAddress((void**)&wil, g_wil);
    cudaGetSymbolAddress((void**)&woh, g_woh);
    cudaGetSymbolAddress((void**)&wol, g_wol);
    cudaGetSymbolAddress((void**)&ath, g_ath);
    cudaGetSymbolAddress((void**)&atl, g_atl);

    // beta[p] = tail[p+1] / sum(tail[1..5])
    double alpha[6], tail[7];
    tail[6] = 0.0;
    for (int j = 5; j >= 0; j--) {
        alpha[j] = pow((double)(j + 1), -1.5);
        tail[j] = tail[j + 1] + alpha[j];
    }
    double bsum = tail[1] + tail[2] + tail[3] + tail[4] + tail[5];
    Betas bt;
    for (int p = 0; p < 5; p++) bt.b[p] = (float)(tail[p + 1] / bsum);

    const int M = BATCH * S_LEN;           // 2048
    const int nx = M * DMODEL;             // 2M
    const int nw1 = 3 * DMODEL * DMODEL;   // 3M
    const int nw2 = DMODEL * DMODEL;       // 1M

    cudaFuncSetAttribute(gemm_split, cudaFuncAttributeMaxDynamicSharedMemorySize, 98304);

    split3<<<(nx + nw1 + nw2) / 4 / 256, 256>>>(x, xh, xl, nx,
                                                W_in, wih, wil, nw1,
                                                W_out, woh, wol, nw2);
    gemm_split<<<dim3(3 * DMODEL / 128, M / 128), 256, 98304>>>(
        xh, xl, wih, wil, qkv, M, 3 * DMODEL, DMODEL);
    chunk_kernel<<<BATCH * H_NUM * NCH, 64>>>();
    prefix_kernel<<<NRK, 1024>>>();
    den_kernel<<<BATCH * H_NUM * NCH, 64>>>(bt);
    final_kernel<<<BATCH * H_NUM * NCH, 64>>>(bt);
    gemm_split<<<dim3(DMODEL / 128, M / 128), 256, 98304>>>(
        ath, atl, woh, wol, out, M, DMODEL, DMODEL);
}

// round 12
// speedup vs baseline: 3.5941x; 1.0109x over previous
#include <cuda_runtime.h>
#include <cuda_bf16.h>
#include <cstdint>
#include <cmath>

// Problem constants
#define S_LEN   1024
#define DMODEL  1024
#define H_NUM   16
#define DH      64
#define BATCH   2
#define NCH     32     // chunks along S
#define CHS     32     // chunk length (S_LEN / NCH)

// Scratch (static device globals; no allocation allowed)
__device__ float g_qkv[(size_t)BATCH * S_LEN * 3 * DMODEL];   // 25.2 MB
__device__ float g_ckv[BATCH * H_NUM * 5 * NCH * DH];         // kv chunk sums -> exclusive prefix
__device__ float g_crk[BATCH * H_NUM * 5 * NCH];              // rk chunk sums -> exclusive prefix

// bf16 hi/lo split operands
__device__ __nv_bfloat16 g_xh[(size_t)BATCH * S_LEN * DMODEL];
__device__ __nv_bfloat16 g_xl[(size_t)BATCH * S_LEN * DMODEL];
__device__ __nv_bfloat16 g_wih[(size_t)3 * DMODEL * DMODEL];
__device__ __nv_bfloat16 g_wil[(size_t)3 * DMODEL * DMODEL];
__device__ __nv_bfloat16 g_woh[(size_t)DMODEL * DMODEL];
__device__ __nv_bfloat16 g_wol[(size_t)DMODEL * DMODEL];
__device__ __nv_bfloat16 g_ath[(size_t)BATCH * S_LEN * DMODEL];
__device__ __nv_bfloat16 g_atl[(size_t)BATCH * S_LEN * DMODEL];

struct Betas { float b[5]; };

__device__ __forceinline__ float clampx(float x) {
    return fminf(fmaxf(x, -1.0f + 1e-6f), 1.0f - 1e-6f);
}

__device__ __forceinline__ void cheb5(float x, float t[5]) {
    float x2 = x + x;
    float t1 = x;
    float t2 = x2 * t1 - 1.0f;
    float t3 = x2 * t2 - t1;
    float t4 = x2 * t3 - t2;
    float t5 = x2 * t4 - t3;
    t[0] = t1; t[1] = t2; t[2] = t3; t[3] = t4; t[4] = t5;
}

__device__ __forceinline__ unsigned pack2(__nv_bfloat16 a, __nv_bfloat16 b) {
    __nv_bfloat162 t(a, b);
    return *reinterpret_cast<unsigned*>(&t);
}

__device__ __forceinline__ void ldsm4(unsigned& r0, unsigned& r1, unsigned& r2, unsigned& r3,
                                      unsigned addr) {
    asm volatile("ldmatrix.sync.aligned.m8n8.x4.shared.b16 {%0,%1,%2,%3}, [%4];"
                 : "=r"(r0), "=r"(r1), "=r"(r2), "=r"(r3) : "r"(addr));
}

__device__ __forceinline__ void mma_bf16(float c[4],
                                         unsigned a0, unsigned a1, unsigned a2, unsigned a3,
                                         unsigned b0, unsigned b1) {
    asm volatile(
        "mma.sync.aligned.m16n8k16.row.col.f32.bf16.bf16.f32 "
        "{%0,%1,%2,%3}, {%4,%5,%6,%7}, {%8,%9}, {%0,%1,%2,%3};"
        : "+f"(c[0]), "+f"(c[1]), "+f"(c[2]), "+f"(c[3])
        : "r"(a0), "r"(a1), "r"(a2), "r"(a3), "r"(b0), "r"(b1));
}

#define CP16(dst, src) \
    asm volatile("cp.async.cg.shared.global [%0], [%1], 16;" :: "r"(dst), "l"(src))
#define CP_COMMIT() asm volatile("cp.async.commit_group;")
#define CP_WAIT1()  asm volatile("cp.async.wait_group 1;")
#define CP_WAIT0()  asm volatile("cp.async.wait_group 0;")

// swizzled byte offset inside a 128x32 bf16 tile (64B rows).
__device__ __forceinline__ unsigned swz(int m, int cbyte) {
    return (unsigned)((m << 6) + (cbyte ^ (((m >> 1) & 3) << 4)));
}

// ---------------------------------------------------------------------------
// split3: f32 -> bf16 hi + bf16 lo residual, three tensors in one launch
// ---------------------------------------------------------------------------
__global__ __launch_bounds__(256) void split3(
    const float* __restrict__ a, __nv_bfloat16* __restrict__ ah, __nv_bfloat16* __restrict__ al, int na,
    const float* __restrict__ b, __nv_bfloat16* __restrict__ bh, __nv_bfloat16* __restrict__ bl, int nb,
    const float* __restrict__ c, __nv_bfloat16* __restrict__ ch, __nv_bfloat16* __restrict__ cl, int nc)
{
    int i = (blockIdx.x * blockDim.x + threadIdx.x) * 4;
    const float* src; __nv_bfloat16 *hi, *lo; int off;
    if (i < na)           { src = a; hi = ah; lo = al; off = i; }
    else if (i < na + nb) { src = b; hi = bh; lo = bl; off = i - na; }
    else if (i < na + nb + nc) { src = c; hi = ch; lo = cl; off = i - na - nb; }
    else return;

    float4 v = *(const float4*)(src + off);
    __nv_bfloat16 h0 = __float2bfloat16(v.x), h1 = __float2bfloat16(v.y);
    __nv_bfloat16 h2 = __float2bfloat16(v.z), h3 = __float2bfloat16(v.w);
    __nv_bfloat16 l0 = __float2bfloat16(v.x - __bfloat162float(h0));
    __nv_bfloat16 l1 = __float2bfloat16(v.y - __bfloat162float(h1));
    __nv_bfloat16 l2 = __float2bfloat16(v.z - __bfloat162float(h2));
    __nv_bfloat16 l3 = __float2bfloat16(v.w - __bfloat162float(h3));
    *(uint2*)(hi + off) = make_uint2(pack2(h0, h1), pack2(h2, h3));
    *(uint2*)(lo + off) = make_uint2(pack2(l0, l1), pack2(l2, l3));
}

// ---------------------------------------------------------------------------
// bf16x3 GEMM, pre-split operands, 3-stage cp.async pipeline (1 sync/tile):
//   C[M,N] = (Ah+Al)[M,K] @ (Bh+Bl)[N,K]^T  (drop Al*Bl)
// BM=BN=128, BK=32, 256 threads (8 warps 2x4), warp tile 64x32.
// ---------------------------------------------------------------------------
__global__ __launch_bounds__(256) void gemm_split(
    const __nv_bfloat16* __restrict__ Ahg, const __nv_bfloat16* __restrict__ Alg,
    const __nv_bfloat16* __restrict__ Bhg, const __nv_bfloat16* __restrict__ Blg,
    float* __restrict__ C, int M, int N, int K)
{
    extern __shared__ char dsmem[];
    const unsigned smem_u32 = (unsigned)__cvta_generic_to_shared(dsmem);

    const int tid  = threadIdx.x;
    const int wid  = tid >> 5;
    const int lane = tid & 31;
    const int wm = (wid >> 2) * 64;
    const int wn = (wid & 3) * 32;

    const int bm = blockIdx.y * 128;
    const int bn = blockIdx.x * 128;

    int crow[2], ccb[2];
    size_t aoff[2], boff[2];
    unsigned dsw[2];
#pragma unroll
    for (int i = 0; i < 2; i++) {
        int c = tid + i * 256;
        crow[i] = c >> 2;
        ccb[i]  = (c & 3) * 16;
        aoff[i] = (size_t)(bm + crow[i]) * K * 2 + ccb[i];
        boff[i] = (size_t)(bn + crow[i]) * K * 2 + ccb[i];
        dsw[i]  = swz(crow[i], ccb[i]);
    }
    const char* Ahc = (const char*)Ahg;
    const char* Alc = (const char*)Alg;
    const char* Bhc = (const char*)Bhg;
    const char* Blc = (const char*)Blg;

    auto issue_stage = [&](int stg, int k0) {
        unsigned sb = smem_u32 + (unsigned)stg * 32768u;
        size_t kb = (size_t)k0 * 2;
#pragma unroll
        for (int i = 0; i < 2; i++) {
            unsigned d = sb + dsw[i];
            CP16(d,          Ahc + aoff[i] + kb);
            CP16(d + 8192u,  Alc + aoff[i] + kb);
            CP16(d + 16384u, Bhc + boff[i] + kb);
            CP16(d + 24576u, Blc + boff[i] + kb);
        }
        CP_COMMIT();
    };

    float acc[4][4][4];
#pragma unroll
    for (int i = 0; i < 4; i++)
#pragma unroll
        for (int j = 0; j < 4; j++)
#pragma unroll
            for (int r = 0; r < 4; r++) acc[i][j][r] = 0.0f;

    const int lt = lane >> 3, lr = lane & 7;
    unsigned a_base[4], b_base[2];
#pragma unroll
    for (int mf = 0; mf < 4; mf++) {
        int m = wm + mf * 16 + (lt & 1) * 8 + lr;
        a_base[mf] = swz(m, (lt >> 1) * 16);
    }
#pragma unroll
    for (int np = 0; np < 2; np++) {
        int n = wn + np * 16 + (lt >> 1) * 8 + lr;
        b_base[np] = swz(n, (lt & 1) * 16);
    }

    const int nk = K / 32;
    issue_stage(0, 0);
    issue_stage(1, 32);

    int cur = 0, nxt = 2;
    for (int kt = 0; kt < nk; kt++) {
        if (kt + 2 < nk) { CP_WAIT1(); } else { CP_WAIT0(); }
        __syncthreads();
        if (kt + 2 < nk) issue_stage(nxt, (kt + 2) * 32);

        const unsigned st = smem_u32 + (unsigned)cur * 32768u;
        const unsigned sAh = st, sAl = st + 8192u, sBh = st + 16384u, sBl = st + 24576u;

#pragma unroll
        for (int kk = 0; kk < 2; kk++) {
            const unsigned kb = kk * 32;   // XOR advance (bit 5 within swizzle field)
            unsigned ah[4][4], al[4][4];
#pragma unroll
            for (int mf = 0; mf < 4; mf++) {
                ldsm4(ah[mf][0], ah[mf][1], ah[mf][2], ah[mf][3], sAh + (a_base[mf] ^ kb));
                ldsm4(al[mf][0], al[mf][1], al[mf][2], al[mf][3], sAl + (a_base[mf] ^ kb));
            }
            unsigned bhf[4][2], blf[4][2];
#pragma unroll
            for (int np = 0; np < 2; np++) {
                ldsm4(bhf[2 * np][0], bhf[2 * np][1], bhf[2 * np + 1][0], bhf[2 * np + 1][1],
                      sBh + (b_base[np] ^ kb));
                ldsm4(blf[2 * np][0], blf[2 * np][1], blf[2 * np + 1][0], blf[2 * np + 1][1],
                      sBl + (b_base[np] ^ kb));
            }
            // Pass 1: hh
#pragma unroll
            for (int mf = 0; mf < 4; mf++)
#pragma unroll
                for (int nf = 0; nf < 4; nf++)
                    mma_bf16(acc[mf][nf], ah[mf][0], ah[mf][1], ah[mf][2], ah[mf][3],
                             bhf[nf][0], bhf[nf][1]);
            // Pass 2: hl
#pragma unroll
            for (int mf = 0; mf < 4; mf++)
#pragma unroll
                for (int nf = 0; nf < 4; nf++)
                    mma_bf16(acc[mf][nf], ah[mf][0], ah[mf][1], ah[mf][2], ah[mf][3],
                             blf[nf][0], blf[nf][1]);
            // Pass 3: lh
#pragma unroll
            for (int mf = 0; mf < 4; mf++)
#pragma unroll
                for (int nf = 0; nf < 4; nf++)
                    mma_bf16(acc[mf][nf], al[mf][0], al[mf][1], al[mf][2], al[mf][3],
                             bhf[nf][0], bhf[nf][1]);
        }
        cur = (cur + 1 == 3) ? 0 : cur + 1;
        nxt = (nxt + 1 == 3) ? 0 : nxt + 1;
    }

    const int g = lane >> 2, th = lane & 3;
#pragma unroll
    for (int mf = 0; mf < 4; mf++) {
#pragma unroll
        for (int nf = 0; nf < 4; nf++) {
            int row = bm + wm + mf * 16 + g;
            int col = bn + wn + nf * 8 + 2 * th;
            *(float2*)(C + (size_t)row * N + col) =
                make_float2(acc[mf][nf][0], acc[mf][nf][1]);
            *(float2*)(C + (size_t)(row + 8) * N + col) =
                make_float2(acc[mf][nf][2], acc[mf][nf][3]);
        }
    }
}

// ---------------------------------------------------------------------------
// Phase 1: per-chunk sums of Tk_p(xk)*v per (b,h,chunk,d), plus chunk totals
// ---------------------------------------------------------------------------
__global__ __launch_bounds__(64) void chunk_kernel()
{
    const int blk = blockIdx.x;                 // b*512 + h*32 + c
    const int c = blk & 31, h = (blk >> 5) & 15, b = blk >> 9;
    const int d = threadIdx.x;

    const float* base = g_qkv + ((size_t)(b * S_LEN + c * CHS)) * (3 * DMODEL)
                        + DMODEL + h * DH + d;
    float kv[5] = {0, 0, 0, 0, 0};
    float rk[5] = {0, 0, 0, 0, 0};
#pragma unroll 4
    for (int s = 0; s < CHS; s++) {
        float kval = base[(size_t)s * (3 * DMODEL)];
        float vval = base[(size_t)s * (3 * DMODEL) + DMODEL];
        float t[5];
        cheb5(clampx(kval * 0.125f), t);
#pragma unroll
        for (int p = 0; p < 5; p++) { kv[p] += t[p] * vval; rk[p] += t[p]; }
    }
    const int bh = b * H_NUM + h;
#pragma unroll
    for (int p = 0; p < 5; p++)
        g_ckv[(((size_t)bh * 5 + p) * NCH + c) * DH + d] = kv[p];

    __shared__ float wred[5][2];
    const int lane = d & 31, w = d >> 5;
#pragma unroll
    for (int p = 0; p < 5; p++) {
        float v = rk[p];
#pragma unroll
        for (int o = 16; o > 0; o >>= 1) v += __shfl_down_sync(0xffffffffu, v, o);
        if (lane == 0) wred[p][w] = v;
    }
    __syncthreads();
    if (d == 0) {
#pragma unroll
        for (int p = 0; p < 5; p++)
            g_crk[((size_t)bh * 5 + p) * NCH + c] = wred[p][0] + wred[p][1];
    }
}

// ---------------------------------------------------------------------------
// Phase 2: block-parallel exclusive prefix over chunks.
// One block per bhp (=bh*5+p): 160 blocks x 1024 threads.
// ---------------------------------------------------------------------------
__global__ __launch_bounds__(1024) void prefix_kernel()
{
    const int bhp = blockIdx.x;          // 0..159
    const int tid = threadIdx.x;
    const int c  = tid >> 5;             // 0..31
    const int d0 = tid & 31;             // handles d0 and d0+32

    __shared__ float sm[2][NCH * DH];    // 2 x 8KB double buffer

    const size_t base = (size_t)bhp * NCH * DH;
    sm[0][c * DH + d0]      = g_ckv[base + c * DH + d0];
    sm[0][c * DH + d0 + 32] = g_ckv[base + c * DH + d0 + 32];
    __syncthreads();

    int src = 0;
#pragma unroll
    for (int st = 1; st < NCH; st <<= 1) {
        const int dst = src ^ 1;
        float v0 = sm[src][c * DH + d0];
        float v1 = sm[src][c * DH + d0 + 32];
        if (c >= st) {
            v0 += sm[src][(c - st) * DH + d0];
            v1 += sm[src][(c - st) * DH + d0 + 32];
        }
        sm[dst][c * DH + d0]      = v0;
        sm[dst][c * DH + d0 + 32] = v1;
        __syncthreads();
        src = dst;
    }

    float e0 = (c == 0) ? 0.0f : sm[src][(c - 1) * DH + d0];
    float e1 = (c == 0) ? 0.0f : sm[src][(c - 1) * DH + d0 + 32];
    g_ckv[base + c * DH + d0]      = e0;
    g_ckv[base + c * DH + d0 + 32] = e1;

    if (tid < 32) {
        const size_t rb = (size_t)bhp * NCH;
        float v = g_crk[rb + tid];
        float inc = v;
#pragma unroll
        for (int o = 1; o < 32; o <<= 1) {
            float t = __shfl_up_sync(0xffffffffu, inc, o);
            if (tid >= o) inc += t;
        }
        g_crk[rb + tid] = inc - v;
    }
}

// ---------------------------------------------------------------------------
// Phase 3 (fused den+final): one block per (b,h,chunk); 64 threads.
// Phase A: compute den for the chunk's 32 s values (2-warp d-split, warp scan)
//          into smem.
// Phase B: rescan chunk; numerator + normalize with smem den; emit bf16 hi/lo.
// ---------------------------------------------------------------------------
__global__ __launch_bounds__(64) void den_final_kernel(Betas bt)
{
    const int blk = blockIdx.x;
    const int c = blk & 31, h = (blk >> 5) & 15, b = blk >> 9;
    const int bh = b * H_NUM + h;

    __shared__ float part[10][32];
    __shared__ float sden[CHS];

    // ---- Phase A: den for s = c*CHS + sl, sl = 0..31 ----
    {
        const int sl = threadIdx.x & 31;
        const int w  = threadIdx.x >> 5;
        const int s = c * CHS + sl;
        const float* row = g_qkv + ((size_t)(b * S_LEN + s)) * (3 * DMODEL) + h * DH + w * 32;

        float Aq[5] = {0, 0, 0, 0, 0};
        float Rk[5] = {0, 0, 0, 0, 0};
#pragma unroll
        for (int d4 = 0; d4 < 32; d4 += 4) {
            float4 q4 = *(const float4*)(row + d4);
            float4 k4 = *(const float4*)(row + DMODEL + d4);
            const float qa[4] = {q4.x, q4.y, q4.z, q4.w};
            const float ka[4] = {k4.x, k4.y, k4.z, k4.w};
#pragma unroll
            for (int j = 0; j < 4; j++) {
                float tq[5], tk[5];
                cheb5(clampx(qa[j] * 0.125f), tq);
                cheb5(clampx(ka[j] * 0.125f), tk);
#pragma unroll
                for (int p = 0; p < 5; p++) { Aq[p] += tq[p]; Rk[p] += tk[p]; }
            }
        }

        if (w == 1) {
#pragma unroll
            for (int p = 0; p < 5; p++) { part[p][sl] = Aq[p]; part[5 + p][sl] = Rk[p]; }
        }
        __syncthreads();
        if (w == 0) {
#pragma unroll
            for (int p = 0; p < 5; p++) { Aq[p] += part[p][sl]; Rk[p] += part[5 + p][sl]; }

            float dsum = 0.0f;
#pragma unroll
            for (int p = 0; p < 5; p++) {
                float v = Rk[p];
#pragma unroll
                for (int o = 1; o < 32; o <<= 1) {
                    float t = __shfl_up_sync(0xffffffffu, v, o);
                    if (sl >= o) v += t;
                }
                float C = v + g_crk[((size_t)bh * 5 + p) * NCH + c];
                dsum += bt.b[p] * Aq[p] * C;
            }
            sden[sl] = dsum;
        }
        __syncthreads();
    }

    // ---- Phase B: rescan + output ----
    const int d = threadIdx.x;
    float kv[5];
#pragma unroll
    for (int p = 0; p < 5; p++)
        kv[p] = g_ckv[(((size_t)bh * 5 + p) * NCH + c) * DH + d];

    const float* base = g_qkv + ((size_t)(b * S_LEN + c * CHS)) * (3 * DMODEL) + h * DH + d;
    const size_t obase = ((size_t)(b * S_LEN + c * CHS)) * DMODEL + h * DH + d;

#pragma unroll 4
    for (int s = 0; s < CHS; s++) {
        const float* r = base + (size_t)s * (3 * DMODEL);
        float qv = r[0];
        float kval = r[DMODEL];
        float vval = r[2 * DMODEL];

        float tk[5];
        cheb5(clampx(kval * 0.125f), tk);
#pragma unroll
        for (int p = 0; p < 5; p++) kv[p] += tk[p] * vval;

        float tq[5];
        cheb5(clampx(qv * 0.125f), tq);
        float num = 0.0f;
#pragma unroll
        for (int p = 0; p < 5; p++) num += bt.b[p] * tq[p] * kv[p];

        float res = num / (sden[s] + 1e-7f);
        __nv_bfloat16 hi = __float2bfloat16(res);
        size_t idx = obase + (size_t)s * DMODEL;
        g_ath[idx] = hi;
        g_atl[idx] = __float2bfloat16(res - __bfloat162float(hi));
    }
}

// ---------------------------------------------------------------------------
#define NKV (BATCH * H_NUM * 5 * DH)
#define NRK (BATCH * H_NUM * 5)

extern "C" void kernel_launch(void* const* d_in, const int* in_sizes, int n_in,
                              void* d_out, int out_size)
{
    const float* x     = (const float*)d_in[0];   // (2,1024,1024)
    const float* W_in  = (const float*)d_in[1];   // (3072,1024)
    const float* W_out = (const float*)d_in[2];   // (1024,1024)
    float* out = (float*)d_out;                   // (2,1024,1024)

    float* qkv;
    cudaGetSymbolAddress((void**)&qkv, g_qkv);
    __nv_bfloat16 *xh, *xl, *wih, *wil, *woh, *wol, *ath, *atl;
    cudaGetSymbolAddress((void**)&xh,  g_xh);
    cudaGetSymbolAddress((void**)&xl,  g_xl);
    cudaGetSymbolAddress((void**)&wih, g_wih);
    cudaGetSymbolAddress((void**)&wil, g_wil);
    cudaGetSymbolAddress((void**)&woh, g_woh);
    cudaGetSymbolAddress((void**)&wol, g_wol);
    cudaGetSymbolAddress((void**)&ath, g_ath);
    cudaGetSymbolAddress((void**)&atl, g_atl);

    // beta[p] = tail[p+1] / sum(tail[1..5])
    double alpha[6], tail[7];
    tail[6] = 0.0;
    for (int j = 5; j >= 0; j--) {
        alpha[j] = pow((double)(j + 1), -1.5);
        tail[j] = tail[j + 1] + alpha[j];
    }
    double bsum = tail[1] + tail[2] + tail[3] + tail[4] + tail[5];
    Betas bt;
    for (int p = 0; p < 5; p++) bt.b[p] = (float)(tail[p + 1] / bsum);

    const int M = BATCH * S_LEN;           // 2048
    const int nx = M * DMODEL;             // 2M
    const int nw1 = 3 * DMODEL * DMODEL;   // 3M
    const int nw2 = DMODEL * DMODEL;       // 1M

    cudaFuncSetAttribute(gemm_split, cudaFuncAttributeMaxDynamicSharedMemorySize, 98304);

    split3<<<(nx + nw1 + nw2) / 4 / 256, 256>>>(x, xh, xl, nx,
                                                W_in, wih, wil, nw1,
                                                W_out, woh, wol, nw2);
    gemm_split<<<dim3(3 * DMODEL / 128, M / 128), 256, 98304>>>(
        xh, xl, wih, wil, qkv, M, 3 * DMODEL, DMODEL);
    chunk_kernel<<<BATCH * H_NUM * NCH, 64>>>();
    prefix_kernel<<<NRK, 1024>>>();
    den_final_kernel<<<BATCH * H_NUM * NCH, 64>>>(bt);
    gemm_split<<<dim3(DMODEL / 128, M / 128), 256, 98304>>>(
        ath, atl, woh, wol, out, M, DMODEL, DMODEL);
}